// round 9
// baseline (speedup 1.0000x reference)
#include <cuda_runtime.h>
#include <cuda_bf16.h>
#include <math.h>
#include <cstdint>

#define Bb 2
#define Tt 2048
#define Dd 1024
#define Hh 16
#define HDd 64
#define NEe 17
#define GK 1024

// quant scales: x,ao in ±8 -> Q=4096 (2^12); W in ±0.25 -> Q=131072 (2^17)
#define QA 4096.0f
#define QW 131072.0f
#define SCALE 1.862645149230957e-9f   // 2^-29

// ---------------- scratch globals ----------------
__device__ int8_t g_x8h[Bb*Tt*Dd],  g_x8l[Bb*Tt*Dd];
__device__ int8_t g_wq8h[3*Dd*Dd],  g_wq8l[3*Dd*Dd];     // Wqkv^T [3072,1024]
__device__ int8_t g_wp8h[Dd*Dd],    g_wp8l[Dd*Dd];       // Wproj^T [1024,1024]
__device__ int8_t g_ao8h[Bb*Tt*Dd], g_ao8l[Bb*Tt*Dd];
__device__ __nv_bfloat16 g_qhi[Bb*Hh*Tt*HDd], g_qlo[Bb*Hh*Tt*HDd];   // [b,h,t,d] *0.125
__device__ __nv_bfloat16 g_khi[Bb*Hh*Tt*HDd], g_klo[Bb*Hh*Tt*HDd];   // [b,h,t,d]
__device__ __nv_bfloat16 g_vhi[Bb*Hh*Tt*HDd], g_vlo[Bb*Hh*Tt*HDd];   // [b,h,d,t] key-permuted
__device__ uint32_t g_pack[(size_t)Bb*Tt*Tt];

// ---------------- helpers ----------------
__device__ __forceinline__ uint32_t smem_u32(const void* p) {
    uint32_t a;
    asm("{ .reg .u64 t; cvta.to.shared.u64 t, %1; cvt.u32.u64 %0, t; }" : "=r"(a) : "l"(p));
    return a;
}
__device__ __forceinline__ void ldsm4(uint32_t* r, uint32_t addr) {
    asm volatile("ldmatrix.sync.aligned.m8n8.x4.shared.b16 {%0,%1,%2,%3}, [%4];"
        : "=r"(r[0]), "=r"(r[1]), "=r"(r[2]), "=r"(r[3]) : "r"(addr));
}
__device__ __forceinline__ void mma16816(float* c, const uint32_t* a, const uint32_t* b) {
    asm volatile("mma.sync.aligned.m16n8k16.row.col.f32.bf16.bf16.f32 "
        "{%0,%1,%2,%3}, {%4,%5,%6,%7}, {%8,%9}, {%0,%1,%2,%3};"
        : "+f"(c[0]), "+f"(c[1]), "+f"(c[2]), "+f"(c[3])
        : "r"(a[0]), "r"(a[1]), "r"(a[2]), "r"(a[3]), "r"(b[0]), "r"(b[1]));
}
__device__ __forceinline__ void mma16832(int* c, const uint32_t* a, const uint32_t* b) {
    asm volatile("mma.sync.aligned.m16n8k32.row.col.s32.s8.s8.s32 "
        "{%0,%1,%2,%3}, {%4,%5,%6,%7}, {%8,%9}, {%0,%1,%2,%3};"
        : "+r"(c[0]), "+r"(c[1]), "+r"(c[2]), "+r"(c[3])
        : "r"(a[0]), "r"(a[1]), "r"(a[2]), "r"(a[3]), "r"(b[0]), "r"(b[1]));
}
__device__ __forceinline__ void pk2(float a, float b, uint32_t& hi, uint32_t& lo) {
    __nv_bfloat16 ha = __float2bfloat16(a), hb = __float2bfloat16(b);
    __nv_bfloat162 hh(ha, hb); hi = *(uint32_t*)&hh;
    __nv_bfloat162 ll(__float2bfloat16(a - __bfloat162float(ha)),
                      __float2bfloat16(b - __bfloat162float(hb)));
    lo = *(uint32_t*)&ll;
}
__device__ __forceinline__ void q16(float v, float Q, int8_t& h, int8_t& l) {
    int xi = __float2int_rn(v * Q);
    xi = max(-32512, min(32511, xi));
    int hh = (xi + 128) >> 8;
    h = (int8_t)hh; l = (int8_t)(xi - (hh << 8));
}
__device__ __forceinline__ void cpa16(uint32_t s, const void* g) {
    asm volatile("cp.async.cg.shared.global [%0], [%1], 16;" :: "r"(s), "l"(g));
}
#define CPC()  asm volatile("cp.async.commit_group;" ::: "memory")
#define CPW0() asm volatile("cp.async.wait_group 0;" ::: "memory")

// ---------------- prep kernels ----------------
__global__ __launch_bounds__(256) void qsplit(const float* __restrict__ s,
                                              int8_t* __restrict__ hi,
                                              int8_t* __restrict__ lo, float Q) {
    int i = (blockIdx.x * 256 + threadIdx.x) * 4;
    float4 v = *(const float4*)(s + i);
    float f[4] = {v.x, v.y, v.z, v.w};
    int8_t h[4], l[4];
#pragma unroll
    for (int j = 0; j < 4; j++) q16(f[j], Q, h[j], l[j]);
    *(char4*)&hi[i] = *(char4*)h;
    *(char4*)&lo[i] = *(char4*)l;
}

// W [Kdim, Ndim] row-major -> Wt hi/lo int8 [Ndim, Kdim]
__global__ __launch_bounds__(256) void qtranssplit(const float* __restrict__ W,
                                                   int8_t* __restrict__ thi,
                                                   int8_t* __restrict__ tlo,
                                                   int Kdim, int Ndim, float Q) {
    __shared__ float t[32][33];
    int n0 = blockIdx.x * 32, k0 = blockIdx.y * 32;
    int tx = threadIdx.x, ty = threadIdx.y;
#pragma unroll
    for (int j = 0; j < 32; j += 8)
        t[ty + j][tx] = W[(size_t)(k0 + ty + j) * Ndim + n0 + tx];
    __syncthreads();
#pragma unroll
    for (int j = 0; j < 32; j += 8) {
        int8_t h, l;
        q16(t[tx][ty + j], Q, h, l);
        size_t o = (size_t)(n0 + ty + j) * Kdim + k0 + tx;
        thi[o] = h; tlo[o] = l;
    }
}

__global__ __launch_bounds__(256) void pack_bias(const float* __restrict__ adj,
                                                 const int* __restrict__ ety,
                                                 uint32_t* __restrict__ out) {
    size_t i = ((size_t)blockIdx.x * 256 + threadIdx.x) * 4;
    float4 a = *(const float4*)(adj + i);
    int4 t = *(const int4*)(ety + i);
    uint4 r;
    r.x = ((uint32_t)t.x << 16) | (uint32_t)__bfloat16_as_ushort(__float2bfloat16(a.x));
    r.y = ((uint32_t)t.y << 16) | (uint32_t)__bfloat16_as_ushort(__float2bfloat16(a.y));
    r.z = ((uint32_t)t.z << 16) | (uint32_t)__bfloat16_as_ushort(__float2bfloat16(a.z));
    r.w = ((uint32_t)t.w << 16) | (uint32_t)__bfloat16_as_ushort(__float2bfloat16(a.w));
    *(uint4*)(out + i) = r;
}

// ---------------------------------------------------------------------------
// IMMA GEMM: C[M,Ncols] = A[M,1024] @ Bt[Ncols,1024]^T, int8 16-bit split.
// 128x64 tile, 8 warps (4x2), warp tile 32x32, K-chunk 64 int8, double buffer.
// Exact integer accumulation: C = (65536*hh + 256*cross + ll) * SCALE.
// mode 0: fp32 Cout. mode 1: QKV epilogue -> bf16 hi/lo, Q *0.125,
//   V -> [b,h,d,t] key-permuted.
// ---------------------------------------------------------------------------
#define LDPB 80
#define TA8 (128 * LDPB)                 // 10240
#define TB8 (64 * LDPB)                  // 5120
#define STG8 (2 * TA8 + 2 * TB8)         // 30720

__global__ __launch_bounds__(256)
void imma_gemm(const int8_t* __restrict__ Ah, const int8_t* __restrict__ Al,
               const int8_t* __restrict__ Bh, const int8_t* __restrict__ Bl,
               int Ncols, float* __restrict__ Cout, int mode) {
    extern __shared__ char smem[];
    uint32_t sb = smem_u32(smem);
    int tid = threadIdx.x, wid = tid >> 5, lane = tid & 31;
    int wm = wid & 3, wn = wid >> 2;
    int m0 = blockIdx.y * 128, n0 = blockIdx.x * 64;

    // loaders: A 512 uint4 (2/thread), B 256 uint4 (1/thread... 2 matrices)
    int ra = tid >> 2, ca = (tid & 3) * 16;      // A rows ra, ra+64
    int rb = tid >> 2, cb = (tid & 3) * 16;      // B rows 0..63
    const int8_t* pAh = Ah + (size_t)m0 * GK;
    const int8_t* pAl = Al + (size_t)m0 * GK;
    const int8_t* pBh = Bh + (size_t)n0 * GK;
    const int8_t* pBl = Bl + (size_t)n0 * GK;
    uint32_t dA0 = (uint32_t)(ra * LDPB + ca), dA1 = (uint32_t)((ra + 64) * LDPB + ca);
    uint32_t dB  = (uint32_t)(rb * LDPB + cb);

    uint32_t a_off = (uint32_t)((wm * 32 + (lane & 15)) * LDPB + (lane >> 4) * 16);
    uint32_t b_off = (uint32_t)((wn * 32 + (lane & 7) + (lane >> 4) * 8) * LDPB
                                + ((lane >> 3) & 1) * 16);

    int ahh[2][4][4], axx[2][4][4], all[2][4][4];
#pragma unroll
    for (int i = 0; i < 2; i++)
#pragma unroll
        for (int j = 0; j < 4; j++)
#pragma unroll
            for (int k = 0; k < 4; k++) { ahh[i][j][k] = 0; axx[i][j][k] = 0; all[i][j][k] = 0; }

    uint4 pf[6];
#pragma unroll
    for (int z = 0; z < 1; z++) {
        pf[0] = *(const uint4*)(pAh + (size_t)ra * GK + ca);
        pf[1] = *(const uint4*)(pAh + (size_t)(ra + 64) * GK + ca);
        pf[2] = *(const uint4*)(pAl + (size_t)ra * GK + ca);
        pf[3] = *(const uint4*)(pAl + (size_t)(ra + 64) * GK + ca);
        pf[4] = *(const uint4*)(pBh + (size_t)rb * GK + cb);
        pf[5] = *(const uint4*)(pBl + (size_t)rb * GK + cb);
    }
    {
        char* base = smem;
        *(uint4*)(base + dA0) = pf[0];
        *(uint4*)(base + dA1) = pf[1];
        *(uint4*)(base + TA8 + dA0) = pf[2];
        *(uint4*)(base + TA8 + dA1) = pf[3];
        *(uint4*)(base + 2 * TA8 + dB) = pf[4];
        *(uint4*)(base + 2 * TA8 + TB8 + dB) = pf[5];
    }
    __syncthreads();

    const int NCH = GK / 64;   // 16
    for (int kc = 0; kc < NCH; kc++) {
        int buf = kc & 1;
        if (kc + 1 < NCH) {
            size_t go = (size_t)(kc + 1) * 64;
            pf[0] = *(const uint4*)(pAh + (size_t)ra * GK + go + ca);
            pf[1] = *(const uint4*)(pAh + (size_t)(ra + 64) * GK + go + ca);
            pf[2] = *(const uint4*)(pAl + (size_t)ra * GK + go + ca);
            pf[3] = *(const uint4*)(pAl + (size_t)(ra + 64) * GK + go + ca);
            pf[4] = *(const uint4*)(pBh + (size_t)rb * GK + go + cb);
            pf[5] = *(const uint4*)(pBl + (size_t)rb * GK + go + cb);
        }

        uint32_t sAh = sb + buf * STG8 + a_off;
        uint32_t sAl = sAh + TA8;
        uint32_t sBh = sb + buf * STG8 + 2 * TA8 + b_off;
        uint32_t sBl = sBh + TB8;
#pragma unroll
        for (int ks = 0; ks < 2; ks++) {
            uint32_t kb = (uint32_t)(ks * 32);
            uint32_t ah[2][4], al[2][4];
#pragma unroll
            for (int tm = 0; tm < 2; tm++) {
                uint32_t ro = (uint32_t)(tm * 16 * LDPB);
                ldsm4(ah[tm], sAh + ro + kb);
                ldsm4(al[tm], sAl + ro + kb);
            }
#pragma unroll
            for (int pr = 0; pr < 2; pr++) {
                uint32_t po = (uint32_t)(pr * 16 * LDPB);
                uint32_t bh4[4], bl4[4];
                ldsm4(bh4, sBh + po + kb);
                ldsm4(bl4, sBl + po + kb);
#pragma unroll
                for (int hf = 0; hf < 2; hf++) {
                    int tn = pr * 2 + hf;
#pragma unroll
                    for (int tm = 0; tm < 2; tm++) {
                        mma16832(ahh[tm][tn], ah[tm], bh4 + hf * 2);
                        mma16832(axx[tm][tn], ah[tm], bl4 + hf * 2);
                        mma16832(axx[tm][tn], al[tm], bh4 + hf * 2);
                        mma16832(all[tm][tn], al[tm], bl4 + hf * 2);
                    }
                }
            }
        }

        if (kc + 1 < NCH) {
            char* base = smem + (1 - buf) * STG8;
            *(uint4*)(base + dA0) = pf[0];
            *(uint4*)(base + dA1) = pf[1];
            *(uint4*)(base + TA8 + dA0) = pf[2];
            *(uint4*)(base + TA8 + dA1) = pf[3];
            *(uint4*)(base + 2 * TA8 + dB) = pf[4];
            *(uint4*)(base + 2 * TA8 + TB8 + dB) = pf[5];
            __syncthreads();
        }
    }

    // combine: C = (65536*hh + 256*cross + ll) * SCALE
    float C[2][4][4];
#pragma unroll
    for (int tm = 0; tm < 2; tm++)
#pragma unroll
        for (int tn = 0; tn < 4; tn++)
#pragma unroll
            for (int k = 0; k < 4; k++)
                C[tm][tn][k] = ((float)ahh[tm][tn][k] * 65536.f
                              + (float)axx[tm][tn][k] * 256.f
                              + (float)all[tm][tn][k]) * SCALE;

    int rbase = m0 + wm * 32 + (lane >> 2);
    int cbase = n0 + wn * 32 + (lane & 3) * 2;

    if (mode == 0) {
#pragma unroll
        for (int tm = 0; tm < 2; tm++)
#pragma unroll
            for (int tn = 0; tn < 4; tn++)
#pragma unroll
                for (int half = 0; half < 2; half++) {
                    int m = rbase + tm * 16 + half * 8;
                    *(float2*)&Cout[(size_t)m * Ncols + cbase + tn * 8] =
                        make_float2(C[tm][tn][half * 2], C[tm][tn][half * 2 + 1]);
                }
        return;
    }

    int which = n0 >> 10;
    if (which < 2) {
        float sc = (which == 0) ? 0.125f : 1.0f;
        __nv_bfloat16* dh = which ? g_khi : g_qhi;
        __nv_bfloat16* dl = which ? g_klo : g_qlo;
#pragma unroll
        for (int tm = 0; tm < 2; tm++)
#pragma unroll
            for (int tn = 0; tn < 4; tn++)
#pragma unroll
                for (int half = 0; half < 2; half++) {
                    int m = rbase + tm * 16 + half * 8;
                    int n = cbase + tn * 8;
                    int h = (n & 1023) >> 6, d = n & 63;
                    int bI = m >> 11, t = m & 2047;
                    size_t ix = ((size_t)(bI * Hh + h) * Tt + t) * HDd + d;
                    uint32_t uh, ul;
                    pk2(C[tm][tn][half * 2] * sc, C[tm][tn][half * 2 + 1] * sc, uh, ul);
                    *(uint32_t*)&dh[ix] = uh;
                    *(uint32_t*)&dl[ix] = ul;
                }
    } else {
        // V: transpose [64 n][128 m] via smem, store [b,h,d,t] key-permuted
        float* buf = (float*)smem;
        __syncthreads();
#pragma unroll
        for (int tm = 0; tm < 2; tm++)
#pragma unroll
            for (int tn = 0; tn < 4; tn++)
#pragma unroll
                for (int half = 0; half < 2; half++) {
                    int nl = wn * 32 + tn * 8 + (lane & 3) * 2;
                    int ml = wm * 32 + (lane >> 2) + tm * 16 + half * 8;
                    buf[nl * 132 + ml]       = C[tm][tn][half * 2];
                    buf[(nl + 1) * 132 + ml] = C[tm][tn][half * 2 + 1];
                }
        __syncthreads();
        int nl = tid >> 2, mq = (tid & 3) * 32;
        int n = n0 + nl;
        int h = (n & 1023) >> 6, d = n & 63;
        int bI = m0 >> 11, t0 = m0 & 2047;
        int gb = mq & 64, co0 = mq & 32;
        size_t base = ((size_t)(bI * Hh + h) * HDd + d) * Tt + t0 + gb;
#pragma unroll
        for (int g = 0; g < 4; g++) {
            __nv_bfloat16 hi8[8], lo8[8];
#pragma unroll
            for (int e = 0; e < 8; e++) {
                int c = co0 + g * 8 + e;
                int src = 16 * ((c >> 1) & 3) + 2 * (c >> 3) + (c & 1);
                float f = buf[nl * 132 + gb + src];
                hi8[e] = __float2bfloat16(f);
                lo8[e] = __float2bfloat16(f - __bfloat162float(hi8[e]));
            }
            *(uint4*)&g_vhi[base + co0 + g * 8] = *(uint4*)hi8;
            *(uint4*)&g_vlo[base + co0 + g * 8] = *(uint4*)lo8;
        }
    }
}

// ---------------------------------------------------------------------------
// HMMA flash attention: q-tile 128, k-tile 64, cp.async double-buffered KV,
// LPT ordering. Finalize writes int8 hi/lo ao for the proj IMMA GEMM.
// ---------------------------------------------------------------------------
#define LQ 72
#define QB (128 * LQ * 2)
#define TB (64 * LQ * 2)
#define OKV (2 * QB)

__global__ __launch_bounds__(256, 2) void attn_mma(
    const uint32_t* __restrict__ pk, const float* __restrict__ adj_bias,
    const float* __restrict__ edge_table) {
    extern __shared__ char sm[];
    uint32_t sB = smem_u32(sm);
    float* ets = (float*)(sm + OKV + 8 * TB);

    int tid = threadIdx.x, w = tid >> 5, lane = tid & 31;
    int qt = (int)(gridDim.x - 1 - blockIdx.x);
    int h = blockIdx.y, b = blockIdx.z;
    int q0 = qt * 128, qw = q0 + 16 * w;
    float bco = adj_bias[h];
    if (tid < NEe) ets[tid] = edge_table[tid * Hh + h];

    {   // Q tile (pre-scaled bf16 hi/lo)
        const __nv_bfloat16* qh = g_qhi + ((size_t)(b * Hh + h) * Tt + q0) * HDd;
        const __nv_bfloat16* ql = g_qlo + ((size_t)(b * Hh + h) * Tt + q0) * HDd;
        __nv_bfloat16* sQh = (__nv_bfloat16*)sm;
        __nv_bfloat16* sQl = sQh + 128 * LQ;
        int r = tid >> 1, cg = (tid & 1) * 32;
#pragma unroll
        for (int u = 0; u < 4; u++) {
            *(uint4*)&sQh[r * LQ + cg + u * 8] = *(const uint4*)&qh[(size_t)r * 64 + cg + u * 8];
            *(uint4*)&sQl[r * LQ + cg + u * 8] = *(const uint4*)&ql[(size_t)r * 64 + cg + u * 8];
        }
    }

    int c = tid >> 2, dg = (tid & 3) * 16;
    int gkp = 16 * ((c >> 1) & 3) + 2 * (c >> 3) + (c & 1);
    uint32_t krow = (uint32_t)(c * LQ + dg) * 2;
    const __nv_bfloat16* bkh = g_khi + ((size_t)(b * Hh + h) * Tt + gkp) * HDd + dg;
    const __nv_bfloat16* bkl = g_klo + ((size_t)(b * Hh + h) * Tt + gkp) * HDd + dg;
    const __nv_bfloat16* bvh = g_vhi + ((size_t)(b * Hh + h) * HDd + c) * Tt + dg;
    const __nv_bfloat16* bvl = g_vlo + ((size_t)(b * Hh + h) * HDd + c) * Tt + dg;

#define LOADKV(jt, bf) do {                                                     \
    int _k0 = (jt) * 64;                                                        \
    uint32_t _bs = sB + OKV + (bf) * 4 * TB;                                    \
    cpa16(_bs + krow,               bkh + (size_t)_k0 * HDd);                   \
    cpa16(_bs + krow + 16,          bkh + (size_t)_k0 * HDd + 8);               \
    cpa16(_bs + TB + krow,          bkl + (size_t)_k0 * HDd);                   \
    cpa16(_bs + TB + krow + 16,     bkl + (size_t)_k0 * HDd + 8);               \
    cpa16(_bs + 2 * TB + krow,      bvh + _k0);                                 \
    cpa16(_bs + 2 * TB + krow + 16, bvh + _k0 + 8);                             \
    cpa16(_bs + 3 * TB + krow,      bvl + _k0);                                 \
    cpa16(_bs + 3 * TB + krow + 16, bvl + _k0 + 8);                             \
    CPC();                                                                      \
} while (0)

    float o[8][4];
#pragma unroll
    for (int i = 0; i < 8; i++)
#pragma unroll
        for (int j = 0; j < 4; j++) o[i][j] = 0.f;
    float m0r = -1e30f, m1r = -1e30f, l0r = 0.f, l1r = 0.f;

    LOADKV(0, 0);

    int nkt = 2 * qt + 2;
    for (int jt = 0; jt < nkt; jt++) {
        int k0 = jt * 64;
        int buf = jt & 1;
        CPW0();
        __syncthreads();
        if (jt + 1 < nkt) LOADKV(jt + 1, buf ^ 1);

        if (k0 > qw + 15) continue;

        uint32_t oKh = OKV + buf * 4 * TB, oKl = oKh + TB, oVh = oKl + TB, oVl = oVh + TB;

        float s[8][4];
#pragma unroll
        for (int i = 0; i < 8; i++)
#pragma unroll
            for (int j = 0; j < 4; j++) s[i][j] = 0.f;

        uint32_t acol = (uint32_t)((lane >> 4) * 8) * 2;
        uint32_t arow = (uint32_t)((16 * w + (lane & 15)) * LQ) * 2;
        uint32_t bro  = (uint32_t)(((lane & 7) + (lane >> 4) * 8) * LQ) * 2;
        uint32_t bco2 = (uint32_t)(((lane >> 3) & 1) * 8) * 2;
#pragma unroll
        for (int ck = 0; ck < 4; ck++) {
            uint32_t kb = (uint32_t)(ck * 16) * 2;
            uint32_t aqh[4], aql[4];
            ldsm4(aqh, sB + arow + acol + kb);
            ldsm4(aql, sB + QB + arow + acol + kb);
#pragma unroll
            for (int pr = 0; pr < 4; pr++) {
                uint32_t ro = (uint32_t)(pr * 16 * LQ) * 2;
                uint32_t bh[4], bl[4];
                ldsm4(bh, sB + oKh + bro + ro + bco2 + kb);
                ldsm4(bl, sB + oKl + bro + ro + bco2 + kb);
#pragma unroll
                for (int hf = 0; hf < 2; hf++) {
                    int tn = pr * 2 + hf;
                    mma16816(s[tn], aqh, bh + hf * 2);
                    mma16816(s[tn], aqh, bl + hf * 2);
                    mma16816(s[tn], aql, bh + hf * 2);
                }
            }
        }

        int a = lane & 3, grp = lane >> 2;
        bool mm = (k0 + 63 > qw);
        float alpha0, alpha1;
#pragma unroll
        for (int half = 0; half < 2; half++) {
            int q = qw + grp + 8 * half;
            const uint4* bp = (const uint4*)(pk + ((size_t)b * Tt + q) * Tt + k0 + 16 * a);
            uint4 u[4] = {bp[0], bp[1], bp[2], bp[3]};
            const uint32_t* ub = (const uint32_t*)u;
            float mx = -1e30f;
#pragma unroll
            for (int nt = 0; nt < 8; nt++)
#pragma unroll
                for (int e = 0; e < 2; e++) {
                    int kk = 2 * nt + e;
                    uint32_t pv = ub[kk];
                    float sv = s[nt][half * 2 + e] + bco * __uint_as_float(pv << 16)
                               + ets[pv >> 16];
                    if (mm && (k0 + 16 * a + kk > q)) sv = -1e30f;
                    s[nt][half * 2 + e] = sv;
                    mx = fmaxf(mx, sv);
                }
            mx = fmaxf(mx, __shfl_xor_sync(0xffffffffu, mx, 1));
            mx = fmaxf(mx, __shfl_xor_sync(0xffffffffu, mx, 2));
            float mold = half ? m1r : m0r;
            float mnew = fmaxf(mold, mx);
            float sum = 0.f;
#pragma unroll
            for (int nt = 0; nt < 8; nt++)
#pragma unroll
                for (int e = 0; e < 2; e++) {
                    float p = __expf(s[nt][half * 2 + e] - mnew);
                    s[nt][half * 2 + e] = p;
                    sum += p;
                }
            sum += __shfl_xor_sync(0xffffffffu, sum, 1);
            sum += __shfl_xor_sync(0xffffffffu, sum, 2);
            float al = __expf(mold - mnew);
            if (half == 0) { m0r = mnew; l0r = l0r * al + sum; alpha0 = al; }
            else           { m1r = mnew; l1r = l1r * al + sum; alpha1 = al; }
        }

#pragma unroll
        for (int nt = 0; nt < 8; nt++) {
            o[nt][0] *= alpha0; o[nt][1] *= alpha0;
            o[nt][2] *= alpha1; o[nt][3] *= alpha1;
        }
#pragma unroll
        for (int j = 0; j < 4; j++) {
            uint32_t ah[4], al2[4];
            pk2(s[2*j][0],   s[2*j][1],   ah[0], al2[0]);
            pk2(s[2*j][2],   s[2*j][3],   ah[1], al2[1]);
            pk2(s[2*j+1][0], s[2*j+1][1], ah[2], al2[2]);
            pk2(s[2*j+1][2], s[2*j+1][3], ah[3], al2[3]);
            uint32_t kb = (uint32_t)(j * 16) * 2;
#pragma unroll
            for (int pr = 0; pr < 4; pr++) {
                uint32_t ro = (uint32_t)(pr * 16 * LQ) * 2;
                uint32_t vh[4], vl[4];
                ldsm4(vh, sB + oVh + bro + ro + bco2 + kb);
                ldsm4(vl, sB + oVl + bro + ro + bco2 + kb);
#pragma unroll
                for (int hf = 0; hf < 2; hf++) {
                    int tn = pr * 2 + hf;
                    mma16816(o[tn], ah, vh + hf * 2);
                    mma16816(o[tn], ah, vl + hf * 2);
                    mma16816(o[tn], al2, vh + hf * 2);
                }
            }
        }
    }

    // finalize -> int8 hi/lo for proj IMMA
    float il0 = 1.f / l0r, il1 = 1.f / l1r;
    int grp = lane >> 2;
    size_t ix = ((size_t)b * Tt + qw + grp) * Dd + h * 64 + (lane & 3) * 2;
#pragma unroll
    for (int nt = 0; nt < 8; nt++) {
        int8_t h0, l0, h1, l1;
        q16(o[nt][0] * il0, QA, h0, l0);
        q16(o[nt][1] * il0, QA, h1, l1);
        *(uchar2*)&g_ao8h[ix + nt * 8] = make_uchar2((unsigned char)h0, (unsigned char)h1);
        *(uchar2*)&g_ao8l[ix + nt * 8] = make_uchar2((unsigned char)l0, (unsigned char)l1);
        q16(o[nt][2] * il1, QA, h0, l0);
        q16(o[nt][3] * il1, QA, h1, l1);
        *(uchar2*)&g_ao8h[ix + 8 * Dd + nt * 8] = make_uchar2((unsigned char)h0, (unsigned char)h1);
        *(uchar2*)&g_ao8l[ix + 8 * Dd + nt * 8] = make_uchar2((unsigned char)l0, (unsigned char)l1);
    }
}

// ---------------------------------------------------------------------------
extern "C" void kernel_launch(void* const* d_in, const int* in_sizes, int n_in,
                              void* d_out, int out_size) {
    const float* x     = (const float*)d_in[0];
    const float* gadj  = (const float*)d_in[1];
    const int*   etyp  = (const int*)d_in[2];
    const float* wqkv  = (const float*)d_in[3];
    const float* wproj = (const float*)d_in[4];
    const float* abias = (const float*)d_in[5];
    const float* etab  = (const float*)d_in[6];
    float* out = (float*)d_out;

    int8_t *x8h, *x8l, *wq8h, *wq8l, *wp8h, *wp8l, *ao8h, *ao8l;
    uint32_t* packp;
    cudaGetSymbolAddress((void**)&x8h,  g_x8h);  cudaGetSymbolAddress((void**)&x8l,  g_x8l);
    cudaGetSymbolAddress((void**)&wq8h, g_wq8h); cudaGetSymbolAddress((void**)&wq8l, g_wq8l);
    cudaGetSymbolAddress((void**)&wp8h, g_wp8h); cudaGetSymbolAddress((void**)&wp8l, g_wp8l);
    cudaGetSymbolAddress((void**)&ao8h, g_ao8h); cudaGetSymbolAddress((void**)&ao8l, g_ao8l);
    cudaGetSymbolAddress((void**)&packp, g_pack);

    const int SHM = 2 * STG8;                        // 61440
    cudaFuncSetAttribute(imma_gemm, cudaFuncAttributeMaxDynamicSharedMemorySize, SHM);
    const int SMA = OKV + 8 * TB + 128;              // 110720
    cudaFuncSetAttribute(attn_mma, cudaFuncAttributeMaxDynamicSharedMemorySize, SMA);

    qsplit<<<(Bb * Tt * Dd) / 1024, 256>>>(x, x8h, x8l, QA);
    qtranssplit<<<dim3(3 * Dd / 32, Dd / 32), dim3(32, 8)>>>(wqkv, wq8h, wq8l, Dd, 3 * Dd, QW);
    qtranssplit<<<dim3(Dd / 32, Dd / 32), dim3(32, 8)>>>(wproj, wp8h, wp8l, Dd, Dd, QW);
    pack_bias<<<(int)(((size_t)Bb * Tt * Tt) / 1024), 256>>>(gadj, etyp, packp);

    imma_gemm<<<dim3(3 * Dd / 64, Bb * Tt / 128), 256, SHM>>>(
        x8h, x8l, wq8h, wq8l, 3 * Dd, nullptr, 1);

    attn_mma<<<dim3(Tt / 128, Hh, Bb), 256, SMA>>>(packp, abias, etab);

    imma_gemm<<<dim3(Dd / 64, Bb * Tt / 128), 256, SHM>>>(
        ao8h, ao8l, wp8h, wp8l, Dd, out, 0);
}

// round 10
// speedup vs baseline: 2.1238x; 2.1238x over previous
#include <cuda_runtime.h>
#include <cuda_bf16.h>
#include <math.h>
#include <cstdint>

#define Bb 2
#define Tt 2048
#define Dd 1024
#define Hh 16
#define HDd 64
#define NEe 17
#define GK 1024

// ---------------- scratch globals ----------------
__device__ __nv_bfloat16 g_xhi[Bb*Tt*Dd],  g_xlo[Bb*Tt*Dd];
__device__ __nv_bfloat16 g_wqThi[3*Dd*Dd], g_wqTlo[3*Dd*Dd];
__device__ __nv_bfloat16 g_wpThi[Dd*Dd],   g_wpTlo[Dd*Dd];
__device__ __nv_bfloat16 g_qhi[Bb*Hh*Tt*HDd], g_qlo[Bb*Hh*Tt*HDd];   // [b,h,t,d] *0.125
__device__ __nv_bfloat16 g_khi[Bb*Hh*Tt*HDd], g_klo[Bb*Hh*Tt*HDd];   // [b,h,t,d]
__device__ __nv_bfloat16 g_vhi[Bb*Hh*Tt*HDd], g_vlo[Bb*Hh*Tt*HDd];   // [b,h,d,t] key-permuted
__device__ __nv_bfloat16 g_aohi[Bb*Tt*Dd], g_aolo[Bb*Tt*Dd];
__device__ uint32_t g_pack[(size_t)Bb*Tt*Tt];

// ---------------- helpers ----------------
__device__ __forceinline__ uint32_t smem_u32(const void* p) {
    uint32_t a;
    asm("{ .reg .u64 t; cvta.to.shared.u64 t, %1; cvt.u32.u64 %0, t; }" : "=r"(a) : "l"(p));
    return a;
}
__device__ __forceinline__ void ldsm4(uint32_t* r, uint32_t addr) {
    asm volatile("ldmatrix.sync.aligned.m8n8.x4.shared.b16 {%0,%1,%2,%3}, [%4];"
        : "=r"(r[0]), "=r"(r[1]), "=r"(r[2]), "=r"(r[3]) : "r"(addr));
}
__device__ __forceinline__ void mma16816(float* c, const uint32_t* a, const uint32_t* b) {
    asm volatile("mma.sync.aligned.m16n8k16.row.col.f32.bf16.bf16.f32 "
        "{%0,%1,%2,%3}, {%4,%5,%6,%7}, {%8,%9}, {%0,%1,%2,%3};"
        : "+f"(c[0]), "+f"(c[1]), "+f"(c[2]), "+f"(c[3])
        : "r"(a[0]), "r"(a[1]), "r"(a[2]), "r"(a[3]), "r"(b[0]), "r"(b[1]));
}
__device__ __forceinline__ void pk2(float a, float b, uint32_t& hi, uint32_t& lo) {
    __nv_bfloat16 ha = __float2bfloat16(a), hb = __float2bfloat16(b);
    __nv_bfloat162 hh(ha, hb); hi = *(uint32_t*)&hh;
    __nv_bfloat162 ll(__float2bfloat16(a - __bfloat162float(ha)),
                      __float2bfloat16(b - __bfloat162float(hb)));
    lo = *(uint32_t*)&ll;
}
__device__ __forceinline__ void cpa16(uint32_t s, const void* g) {
    asm volatile("cp.async.cg.shared.global [%0], [%1], 16;" :: "r"(s), "l"(g));
}
#define CPC()  asm volatile("cp.async.commit_group;" ::: "memory")
#define CPW0() asm volatile("cp.async.wait_group 0;" ::: "memory")

// ---------------- prep kernels ----------------
__global__ __launch_bounds__(256) void split_kernel(const float* __restrict__ s,
                                                    __nv_bfloat16* __restrict__ hi,
                                                    __nv_bfloat16* __restrict__ lo) {
    int i = (blockIdx.x * 256 + threadIdx.x) * 4;
    float4 v = *(const float4*)(s + i);
    float f[4] = {v.x, v.y, v.z, v.w};
    __nv_bfloat16 h[4], l[4];
#pragma unroll
    for (int j = 0; j < 4; j++) {
        h[j] = __float2bfloat16(f[j]);
        l[j] = __float2bfloat16(f[j] - __bfloat162float(h[j]));
    }
    *(__nv_bfloat162*)&hi[i]     = __nv_bfloat162(h[0], h[1]);
    *(__nv_bfloat162*)&hi[i + 2] = __nv_bfloat162(h[2], h[3]);
    *(__nv_bfloat162*)&lo[i]     = __nv_bfloat162(l[0], l[1]);
    *(__nv_bfloat162*)&lo[i + 2] = __nv_bfloat162(l[2], l[3]);
}

__global__ __launch_bounds__(256) void transsplit(const float* __restrict__ W,
                                                  __nv_bfloat16* __restrict__ thi,
                                                  __nv_bfloat16* __restrict__ tlo,
                                                  int Kdim, int Ndim) {
    __shared__ float t[32][33];
    int n0 = blockIdx.x * 32, k0 = blockIdx.y * 32;
    int tx = threadIdx.x, ty = threadIdx.y;
#pragma unroll
    for (int j = 0; j < 32; j += 8)
        t[ty + j][tx] = W[(size_t)(k0 + ty + j) * Ndim + n0 + tx];
    __syncthreads();
#pragma unroll
    for (int j = 0; j < 32; j += 8) {
        float v = t[tx][ty + j];
        __nv_bfloat16 h = __float2bfloat16(v);
        size_t o = (size_t)(n0 + ty + j) * Kdim + k0 + tx;
        thi[o] = h;
        tlo[o] = __float2bfloat16(v - __bfloat162float(h));
    }
}

__global__ __launch_bounds__(256) void pack_bias(const float* __restrict__ adj,
                                                 const int* __restrict__ ety,
                                                 uint32_t* __restrict__ out) {
    size_t i = ((size_t)blockIdx.x * 256 + threadIdx.x) * 4;
    float4 a = *(const float4*)(adj + i);
    int4 t = *(const int4*)(ety + i);
    uint4 r;
    r.x = ((uint32_t)t.x << 16) | (uint32_t)__bfloat16_as_ushort(__float2bfloat16(a.x));
    r.y = ((uint32_t)t.y << 16) | (uint32_t)__bfloat16_as_ushort(__float2bfloat16(a.y));
    r.z = ((uint32_t)t.z << 16) | (uint32_t)__bfloat16_as_ushort(__float2bfloat16(a.z));
    r.w = ((uint32_t)t.w << 16) | (uint32_t)__bfloat16_as_ushort(__float2bfloat16(a.w));
    *(uint4*)(out + i) = r;
}

// ---------------------------------------------------------------------------
// HMMA GEMM (R5/R8 version): 128x128 tile, LDG prefetch double-buffer.
// ---------------------------------------------------------------------------
#define KC 32
#define LDP 40
#define TILE_B (128 * LDP * 2)
#define BUF_B  (4 * TILE_B)

__global__ __launch_bounds__(256)
void mma_gemm(const __nv_bfloat16* __restrict__ Ahi, const __nv_bfloat16* __restrict__ Alo,
              const __nv_bfloat16* __restrict__ Bhi, const __nv_bfloat16* __restrict__ Blo,
              int Ncols, float* __restrict__ Cout, int mode) {
    extern __shared__ char smem[];
    uint32_t sb = smem_u32(smem);
    int tid = threadIdx.x, wid = tid >> 5, lane = tid & 31;
    int wm = wid & 3, wn = wid >> 2;
    int m0 = blockIdx.y * 128, n0 = blockIdx.x * 128;

    int r_ld  = tid >> 2;
    int c8_ld = (tid & 3) * 8;
    const __nv_bfloat16* srcs[4] = {
        Ahi + (size_t)m0 * GK, Alo + (size_t)m0 * GK,
        Bhi + (size_t)n0 * GK, Blo + (size_t)n0 * GK };

    uint32_t a_off = (uint32_t)((wm * 32 + (lane & 15)) * LDP + (lane >> 4) * 8) * 2;
    uint32_t b_off = (uint32_t)((wn * 64 + (lane & 7) + (lane >> 4) * 8) * LDP
                                + ((lane >> 3) & 1) * 8) * 2;

    float acc[2][8][4];
#pragma unroll
    for (int i = 0; i < 2; i++)
#pragma unroll
        for (int j = 0; j < 8; j++)
#pragma unroll
            for (int k = 0; k < 4; k++) acc[i][j][k] = 0.f;

    uint4 pf[4][2];
#pragma unroll
    for (int t = 0; t < 4; t++)
#pragma unroll
        for (int i = 0; i < 2; i++)
            pf[t][i] = *(const uint4*)(srcs[t] + (size_t)(r_ld + i * 64) * GK + c8_ld);
    {
        char* base = smem;
#pragma unroll
        for (int t = 0; t < 4; t++)
#pragma unroll
            for (int i = 0; i < 2; i++)
                *(uint4*)(base + t * TILE_B + ((r_ld + i * 64) * LDP + c8_ld) * 2) = pf[t][i];
    }
    __syncthreads();

    const int NCH = GK / KC;
    for (int kc = 0; kc < NCH; kc++) {
        int buf = kc & 1;
        if (kc + 1 < NCH) {
            size_t go = (size_t)(kc + 1) * KC;
#pragma unroll
            for (int t = 0; t < 4; t++)
#pragma unroll
                for (int i = 0; i < 2; i++)
                    pf[t][i] = *(const uint4*)(srcs[t] + (size_t)(r_ld + i * 64) * GK + go + c8_ld);
        }
        uint32_t sAh = sb + buf * BUF_B + a_off;
        uint32_t sAl = sAh + TILE_B;
        uint32_t sBh = sb + buf * BUF_B + 2 * TILE_B + b_off;
        uint32_t sBl = sBh + TILE_B;
#pragma unroll
        for (int ks = 0; ks < 2; ks++) {
            uint32_t kb = (uint32_t)(ks * 16) * 2;
            uint32_t ah[2][4], al[2][4];
#pragma unroll
            for (int tm = 0; tm < 2; tm++) {
                uint32_t ro = (uint32_t)(tm * 16 * LDP) * 2;
                ldsm4(ah[tm], sAh + ro + kb);
                ldsm4(al[tm], sAl + ro + kb);
            }
#pragma unroll
            for (int pr = 0; pr < 4; pr++) {
                uint32_t po = (uint32_t)(pr * 16 * LDP) * 2;
                uint32_t bh[4], bl[4];
                ldsm4(bh, sBh + po + kb);
                ldsm4(bl, sBl + po + kb);
#pragma unroll
                for (int hf = 0; hf < 2; hf++) {
                    int tn = pr * 2 + hf;
#pragma unroll
                    for (int tm = 0; tm < 2; tm++) {
                        mma16816(acc[tm][tn], ah[tm], bh + hf * 2);
                        mma16816(acc[tm][tn], ah[tm], bl + hf * 2);
                        mma16816(acc[tm][tn], al[tm], bh + hf * 2);
                    }
                }
            }
        }
        if (kc + 1 < NCH) {
            char* base = smem + (1 - buf) * BUF_B;
#pragma unroll
            for (int t = 0; t < 4; t++)
#pragma unroll
                for (int i = 0; i < 2; i++)
                    *(uint4*)(base + t * TILE_B + ((r_ld + i * 64) * LDP + c8_ld) * 2) = pf[t][i];
            __syncthreads();
        }
    }

    int rbase = m0 + wm * 32 + (lane >> 2);
    int cbase = n0 + wn * 64 + (lane & 3) * 2;

    if (mode == 0) {
#pragma unroll
        for (int tm = 0; tm < 2; tm++)
#pragma unroll
            for (int tn = 0; tn < 8; tn++)
#pragma unroll
                for (int half = 0; half < 2; half++) {
                    int m = rbase + tm * 16 + half * 8;
                    *(float2*)&Cout[(size_t)m * Ncols + cbase + tn * 8] =
                        make_float2(acc[tm][tn][half * 2], acc[tm][tn][half * 2 + 1]);
                }
        return;
    }

    int which = n0 >> 10;
    if (which < 2) {
        float sc = (which == 0) ? 0.125f : 1.0f;
        __nv_bfloat16* dh = which ? g_khi : g_qhi;
        __nv_bfloat16* dl = which ? g_klo : g_qlo;
#pragma unroll
        for (int tm = 0; tm < 2; tm++)
#pragma unroll
            for (int tn = 0; tn < 8; tn++)
#pragma unroll
                for (int half = 0; half < 2; half++) {
                    int m = rbase + tm * 16 + half * 8;
                    int n = cbase + tn * 8;
                    int h = (n & 1023) >> 6, d = n & 63;
                    int bI = m >> 11, t = m & 2047;
                    size_t ix = ((size_t)(bI * Hh + h) * Tt + t) * HDd + d;
                    uint32_t uh, ul;
                    pk2(acc[tm][tn][half * 2] * sc, acc[tm][tn][half * 2 + 1] * sc, uh, ul);
                    *(uint32_t*)&dh[ix] = uh;
                    *(uint32_t*)&dl[ix] = ul;
                }
    } else {
        float* buf = (float*)smem;
        __syncthreads();
#pragma unroll
        for (int tm = 0; tm < 2; tm++)
#pragma unroll
            for (int tn = 0; tn < 8; tn++)
#pragma unroll
                for (int half = 0; half < 2; half++) {
                    int nl = wn * 64 + tn * 8 + (lane & 3) * 2;
                    int ml = wm * 32 + (lane >> 2) + tm * 16 + half * 8;
                    buf[nl * 132 + ml]       = acc[tm][tn][half * 2];
                    buf[(nl + 1) * 132 + ml] = acc[tm][tn][half * 2 + 1];
                }
        __syncthreads();
        int nl = tid >> 1, mh = (tid & 1) * 64;
        int n = n0 + nl;
        int h = (n & 1023) >> 6, d = n & 63;
        int bI = m0 >> 11, t0 = (m0 & 2047) + mh;
        size_t base = ((size_t)(bI * Hh + h) * HDd + d) * Tt + t0;
#pragma unroll
        for (int g = 0; g < 8; g++) {
            __nv_bfloat16 hi8[8], lo8[8];
#pragma unroll
            for (int e = 0; e < 8; e++) {
                int c = g * 8 + e;
                int src = 16 * ((c >> 1) & 3) + 2 * (c >> 3) + (c & 1);
                float f = buf[nl * 132 + mh + src];
                hi8[e] = __float2bfloat16(f);
                lo8[e] = __float2bfloat16(f - __bfloat162float(hi8[e]));
            }
            *(uint4*)&g_vhi[base + g * 8] = *(uint4*)hi8;
            *(uint4*)&g_vlo[base + g * 8] = *(uint4*)lo8;
        }
    }
}

// ---------------------------------------------------------------------------
// HMMA flash attention: q-tile 128, k-tile 64, cp.async double-buffered KV,
// LPT ordering, bias loads software-pipelined ahead of the QK^T MMAs.
// ---------------------------------------------------------------------------
#define LQ 72
#define QB (128 * LQ * 2)
#define TB (64 * LQ * 2)
#define OKV (2 * QB)

__global__ __launch_bounds__(256, 2) void attn_mma(
    const uint32_t* __restrict__ pk, const float* __restrict__ adj_bias,
    const float* __restrict__ edge_table) {
    extern __shared__ char sm[];
    uint32_t sB = smem_u32(sm);
    float* ets = (float*)(sm + OKV + 8 * TB);

    int tid = threadIdx.x, w = tid >> 5, lane = tid & 31;
    int qt = (int)(gridDim.x - 1 - blockIdx.x);
    int h = blockIdx.y, b = blockIdx.z;
    int q0 = qt * 128, qw = q0 + 16 * w;
    float bco = adj_bias[h];
    if (tid < NEe) ets[tid] = edge_table[tid * Hh + h];

    {   // Q tile (pre-scaled bf16 hi/lo)
        const __nv_bfloat16* qh = g_qhi + ((size_t)(b * Hh + h) * Tt + q0) * HDd;
        const __nv_bfloat16* ql = g_qlo + ((size_t)(b * Hh + h) * Tt + q0) * HDd;
        __nv_bfloat16* sQh = (__nv_bfloat16*)sm;
        __nv_bfloat16* sQl = sQh + 128 * LQ;
        int r = tid >> 1, cg = (tid & 1) * 32;
#pragma unroll
        for (int u = 0; u < 4; u++) {
            *(uint4*)&sQh[r * LQ + cg + u * 8] = *(const uint4*)&qh[(size_t)r * 64 + cg + u * 8];
            *(uint4*)&sQl[r * LQ + cg + u * 8] = *(const uint4*)&ql[(size_t)r * 64 + cg + u * 8];
        }
    }

    int c = tid >> 2, dg = (tid & 3) * 16;
    int gkp = 16 * ((c >> 1) & 3) + 2 * (c >> 3) + (c & 1);
    uint32_t krow = (uint32_t)(c * LQ + dg) * 2;
    const __nv_bfloat16* bkh = g_khi + ((size_t)(b * Hh + h) * Tt + gkp) * HDd + dg;
    const __nv_bfloat16* bkl = g_klo + ((size_t)(b * Hh + h) * Tt + gkp) * HDd + dg;
    const __nv_bfloat16* bvh = g_vhi + ((size_t)(b * Hh + h) * HDd + c) * Tt + dg;
    const __nv_bfloat16* bvl = g_vlo + ((size_t)(b * Hh + h) * HDd + c) * Tt + dg;

#define LOADKV(jt, bf) do {                                                     \
    int _k0 = (jt) * 64;                                                        \
    uint32_t _bs = sB + OKV + (bf) * 4 * TB;                                    \
    cpa16(_bs + krow,               bkh + (size_t)_k0 * HDd);                   \
    cpa16(_bs + krow + 16,          bkh + (size_t)_k0 * HDd + 8);               \
    cpa16(_bs + TB + krow,          bkl + (size_t)_k0 * HDd);                   \
    cpa16(_bs + TB + krow + 16,     bkl + (size_t)_k0 * HDd + 8);               \
    cpa16(_bs + 2 * TB + krow,      bvh + _k0);                                 \
    cpa16(_bs + 2 * TB + krow + 16, bvh + _k0 + 8);                             \
    cpa16(_bs + 3 * TB + krow,      bvl + _k0);                                 \
    cpa16(_bs + 3 * TB + krow + 16, bvl + _k0 + 8);                             \
    CPC();                                                                      \
} while (0)

    float o[8][4];
#pragma unroll
    for (int i = 0; i < 8; i++)
#pragma unroll
        for (int j = 0; j < 4; j++) o[i][j] = 0.f;
    float m0r = -1e30f, m1r = -1e30f, l0r = 0.f, l1r = 0.f;

    LOADKV(0, 0);

    int a = lane & 3, grp = lane >> 2;
    const uint32_t* pkb = pk + ((size_t)b * Tt + qw + grp) * Tt + 16 * a;

    int nkt = 2 * qt + 2;
    for (int jt = 0; jt < nkt; jt++) {
        int k0 = jt * 64;
        int buf = jt & 1;
        CPW0();
        __syncthreads();
        if (jt + 1 < nkt) LOADKV(jt + 1, buf ^ 1);

        if (k0 > qw + 15) continue;

        uint32_t oKh = OKV + buf * 4 * TB, oKl = oKh + TB, oVh = oKl + TB, oVl = oVh + TB;

        // ---- issue half-0 bias loads EARLY (covered by the QK^T MMAs) ----
        uint4 u0[4];
        {
            const uint4* bp0 = (const uint4*)(pkb + k0);
            u0[0] = bp0[0]; u0[1] = bp0[1]; u0[2] = bp0[2]; u0[3] = bp0[3];
        }

        float s[8][4];
#pragma unroll
        for (int i = 0; i < 8; i++)
#pragma unroll
            for (int j = 0; j < 4; j++) s[i][j] = 0.f;

        uint32_t acol = (uint32_t)((lane >> 4) * 8) * 2;
        uint32_t arow = (uint32_t)((16 * w + (lane & 15)) * LQ) * 2;
        uint32_t bro  = (uint32_t)(((lane & 7) + (lane >> 4) * 8) * LQ) * 2;
        uint32_t bco2 = (uint32_t)(((lane >> 3) & 1) * 8) * 2;
#pragma unroll
        for (int ck = 0; ck < 4; ck++) {
            uint32_t kb = (uint32_t)(ck * 16) * 2;
            uint32_t aqh[4], aql[4];
            ldsm4(aqh, sB + arow + acol + kb);
            ldsm4(aql, sB + QB + arow + acol + kb);
#pragma unroll
            for (int pr = 0; pr < 4; pr++) {
                uint32_t ro = (uint32_t)(pr * 16 * LQ) * 2;
                uint32_t bh[4], bl[4];
                ldsm4(bh, sB + oKh + bro + ro + bco2 + kb);
                ldsm4(bl, sB + oKl + bro + ro + bco2 + kb);
#pragma unroll
                for (int hf = 0; hf < 2; hf++) {
                    int tn = pr * 2 + hf;
                    mma16816(s[tn], aqh, bh + hf * 2);
                    mma16816(s[tn], aqh, bl + hf * 2);
                    mma16816(s[tn], aql, bh + hf * 2);
                }
            }
        }

        // ---- issue half-1 bias loads (covered by half-0 softmax ALU) ----
        uint4 u1[4];
        {
            const uint4* bp1 = (const uint4*)(pkb + 8 * Tt + k0);
            u1[0] = bp1[0]; u1[1] = bp1[1]; u1[2] = bp1[2]; u1[3] = bp1[3];
        }

        bool mm = (k0 + 63 > qw);
        float alpha0, alpha1;
#pragma unroll
        for (int half = 0; half < 2; half++) {
            int q = qw + grp + 8 * half;
            const uint32_t* ub = (const uint32_t*)(half ? u1 : u0);
            float mx = -1e30f;
#pragma unroll
            for (int nt = 0; nt < 8; nt++)
#pragma unroll
                for (int e = 0; e < 2; e++) {
                    int kk = 2 * nt + e;
                    uint32_t pv = ub[kk];
                    float sv = s[nt][half * 2 + e] + bco * __uint_as_float(pv << 16)
                               + ets[pv >> 16];
                    if (mm && (k0 + 16 * a + kk > q)) sv = -1e30f;
                    s[nt][half * 2 + e] = sv;
                    mx = fmaxf(mx, sv);
                }
            mx = fmaxf(mx, __shfl_xor_sync(0xffffffffu, mx, 1));
            mx = fmaxf(mx, __shfl_xor_sync(0xffffffffu, mx, 2));
            float mold = half ? m1r : m0r;
            float mnew = fmaxf(mold, mx);
            float sum = 0.f;
#pragma unroll
            for (int nt = 0; nt < 8; nt++)
#pragma unroll
                for (int e = 0; e < 2; e++) {
                    float p = __expf(s[nt][half * 2 + e] - mnew);
                    s[nt][half * 2 + e] = p;
                    sum += p;
                }
            sum += __shfl_xor_sync(0xffffffffu, sum, 1);
            sum += __shfl_xor_sync(0xffffffffu, sum, 2);
            float al = __expf(mold - mnew);
            if (half == 0) { m0r = mnew; l0r = l0r * al + sum; alpha0 = al; }
            else           { m1r = mnew; l1r = l1r * al + sum; alpha1 = al; }
        }

#pragma unroll
        for (int nt = 0; nt < 8; nt++) {
            o[nt][0] *= alpha0; o[nt][1] *= alpha0;
            o[nt][2] *= alpha1; o[nt][3] *= alpha1;
        }
#pragma unroll
        for (int j = 0; j < 4; j++) {
            uint32_t ah[4], al2[4];
            pk2(s[2*j][0],   s[2*j][1],   ah[0], al2[0]);
            pk2(s[2*j][2],   s[2*j][3],   ah[1], al2[1]);
            pk2(s[2*j+1][0], s[2*j+1][1], ah[2], al2[2]);
            pk2(s[2*j+1][2], s[2*j+1][3], ah[3], al2[3]);
            uint32_t kb = (uint32_t)(j * 16) * 2;
#pragma unroll
            for (int pr = 0; pr < 4; pr++) {
                uint32_t ro = (uint32_t)(pr * 16 * LQ) * 2;
                uint32_t vh[4], vl[4];
                ldsm4(vh, sB + oVh + bro + ro + bco2 + kb);
                ldsm4(vl, sB + oVl + bro + ro + bco2 + kb);
#pragma unroll
                for (int hf = 0; hf < 2; hf++) {
                    int tn = pr * 2 + hf;
                    mma16816(o[tn], ah, vh + hf * 2);
                    mma16816(o[tn], ah, vl + hf * 2);
                    mma16816(o[tn], al2, vh + hf * 2);
                }
            }
        }
    }

    float il0 = 1.f / l0r, il1 = 1.f / l1r;
    size_t ix = ((size_t)b * Tt + qw + grp) * Dd + h * 64 + a * 2;
#pragma unroll
    for (int nt = 0; nt < 8; nt++) {
        uint32_t uh, ul;
        pk2(o[nt][0] * il0, o[nt][1] * il0, uh, ul);
        *(uint32_t*)&g_aohi[ix + nt * 8] = uh;
        *(uint32_t*)&g_aolo[ix + nt * 8] = ul;
        pk2(o[nt][2] * il1, o[nt][3] * il1, uh, ul);
        *(uint32_t*)&g_aohi[ix + 8 * Dd + nt * 8] = uh;
        *(uint32_t*)&g_aolo[ix + 8 * Dd + nt * 8] = ul;
    }
}

// ---------------------------------------------------------------------------
extern "C" void kernel_launch(void* const* d_in, const int* in_sizes, int n_in,
                              void* d_out, int out_size) {
    const float* x     = (const float*)d_in[0];
    const float* gadj  = (const float*)d_in[1];
    const int*   etyp  = (const int*)d_in[2];
    const float* wqkv  = (const float*)d_in[3];
    const float* wproj = (const float*)d_in[4];
    const float* abias = (const float*)d_in[5];
    const float* etab  = (const float*)d_in[6];
    float* out = (float*)d_out;

    __nv_bfloat16 *xhi, *xlo, *wqhi, *wqlo, *wphi, *wplo, *aohi, *aolo;
    uint32_t* packp;
    cudaGetSymbolAddress((void**)&xhi,  g_xhi);   cudaGetSymbolAddress((void**)&xlo,  g_xlo);
    cudaGetSymbolAddress((void**)&wqhi, g_wqThi); cudaGetSymbolAddress((void**)&wqlo, g_wqTlo);
    cudaGetSymbolAddress((void**)&wphi, g_wpThi); cudaGetSymbolAddress((void**)&wplo, g_wpTlo);
    cudaGetSymbolAddress((void**)&aohi, g_aohi);  cudaGetSymbolAddress((void**)&aolo, g_aolo);
    cudaGetSymbolAddress((void**)&packp, g_pack);

    const int SHM = 2 * BUF_B;                        // 81920
    cudaFuncSetAttribute(mma_gemm, cudaFuncAttributeMaxDynamicSharedMemorySize, SHM);
    const int SMA = OKV + 8 * TB + 128;               // 110720
    cudaFuncSetAttribute(attn_mma, cudaFuncAttributeMaxDynamicSharedMemorySize, SMA);

    split_kernel<<<(Bb * Tt * Dd) / 1024, 256>>>(x, xhi, xlo);
    transsplit<<<dim3(3 * Dd / 32, Dd / 32), dim3(32, 8)>>>(wqkv, wqhi, wqlo, Dd, 3 * Dd);
    transsplit<<<dim3(Dd / 32, Dd / 32), dim3(32, 8)>>>(wproj, wphi, wplo, Dd, Dd);
    pack_bias<<<(int)(((size_t)Bb * Tt * Tt) / 1024), 256>>>(gadj, etyp, packp);

    mma_gemm<<<dim3(3 * Dd / 128, Bb * Tt / 128), 256, SHM>>>(
        xhi, xlo, wqhi, wqlo, 3 * Dd, nullptr, 1);

    attn_mma<<<dim3(Tt / 128, Hh, Bb), 256, SMA>>>(packp, abias, etab);

    mma_gemm<<<dim3(Dd / 128, Bb * Tt / 128), 256, SHM>>>(
        aohi, aolo, wphi, wplo, Dd, out, 0);
}

// round 12
// speedup vs baseline: 2.7066x; 1.2744x over previous
#include <cuda_runtime.h>
#include <cuda_bf16.h>
#include <cuda_fp16.h>
#include <math.h>
#include <cstdint>

#define Bb 2
#define Tt 2048
#define Dd 1024
#define Hh 16
#define HDd 64
#define NEe 17
#define GK 1024

// ---------------- scratch globals ----------------
__device__ __half g_x16[Bb*Tt*Dd];                                   // x single fp16
__device__ __half g_wq16h[3*Dd*Dd], g_wq16l[3*Dd*Dd];                // Wqkv^T fp16 hi/lo
__device__ __half g_wp16h[Dd*Dd],   g_wp16l[Dd*Dd];                  // Wproj^T fp16 hi/lo
__device__ __half g_ao16[Bb*Tt*Dd];                                  // attn out single fp16
__device__ __nv_bfloat16 g_qhi[Bb*Hh*Tt*HDd], g_qlo[Bb*Hh*Tt*HDd];   // [b,h,t,d] *0.125
__device__ __nv_bfloat16 g_khi[Bb*Hh*Tt*HDd], g_klo[Bb*Hh*Tt*HDd];   // [b,h,t,d]
__device__ __half g_vhi[Bb*Hh*Tt*HDd], g_vlo[Bb*Hh*Tt*HDd];          // [b,h,d,t] fp16, key-permuted
__device__ uint32_t g_pack[(size_t)Bb*Tt*Tt];

// ---------------- helpers ----------------
__device__ __forceinline__ uint32_t smem_u32(const void* p) {
    uint32_t a;
    asm("{ .reg .u64 t; cvta.to.shared.u64 t, %1; cvt.u32.u64 %0, t; }" : "=r"(a) : "l"(p));
    return a;
}
__device__ __forceinline__ void ldsm4(uint32_t* r, uint32_t addr) {
    asm volatile("ldmatrix.sync.aligned.m8n8.x4.shared.b16 {%0,%1,%2,%3}, [%4];"
        : "=r"(r[0]), "=r"(r[1]), "=r"(r[2]), "=r"(r[3]) : "r"(addr));
}
__device__ __forceinline__ void mma16816(float* c, const uint32_t* a, const uint32_t* b) {
    asm volatile("mma.sync.aligned.m16n8k16.row.col.f32.bf16.bf16.f32 "
        "{%0,%1,%2,%3}, {%4,%5,%6,%7}, {%8,%9}, {%0,%1,%2,%3};"
        : "+f"(c[0]), "+f"(c[1]), "+f"(c[2]), "+f"(c[3])
        : "r"(a[0]), "r"(a[1]), "r"(a[2]), "r"(a[3]), "r"(b[0]), "r"(b[1]));
}
__device__ __forceinline__ void mma16816h(float* c, const uint32_t* a, const uint32_t* b) {
    asm volatile("mma.sync.aligned.m16n8k16.row.col.f32.f16.f16.f32 "
        "{%0,%1,%2,%3}, {%4,%5,%6,%7}, {%8,%9}, {%0,%1,%2,%3};"
        : "+f"(c[0]), "+f"(c[1]), "+f"(c[2]), "+f"(c[3])
        : "r"(a[0]), "r"(a[1]), "r"(a[2]), "r"(a[3]), "r"(b[0]), "r"(b[1]));
}
__device__ __forceinline__ void pk2(float a, float b, uint32_t& hi, uint32_t& lo) {
    __nv_bfloat16 ha = __float2bfloat16(a), hb = __float2bfloat16(b);
    __nv_bfloat162 hh(ha, hb); hi = *(uint32_t*)&hh;
    __nv_bfloat162 ll(__float2bfloat16(a - __bfloat162float(ha)),
                      __float2bfloat16(b - __bfloat162float(hb)));
    lo = *(uint32_t*)&ll;
}
__device__ __forceinline__ uint32_t h2u(float a, float b) {
    __half2 v = __floats2half2_rn(a, b);
    return *(uint32_t*)&v;
}
__device__ __forceinline__ void cpa16(uint32_t s, const void* g) {
    asm volatile("cp.async.cg.shared.global [%0], [%1], 16;" :: "r"(s), "l"(g));
}
#define CPC()  asm volatile("cp.async.commit_group;" ::: "memory")
#define CPW0() asm volatile("cp.async.wait_group 0;" ::: "memory")

// ---------------- prep kernels ----------------
__global__ __launch_bounds__(256) void cvt16(const float* __restrict__ s,
                                             __half* __restrict__ d) {
    int i = (blockIdx.x * 256 + threadIdx.x) * 4;
    float4 v = *(const float4*)(s + i);
    __half2 a = __floats2half2_rn(v.x, v.y);
    __half2 b = __floats2half2_rn(v.z, v.w);
    *(__half2*)&d[i]     = a;
    *(__half2*)&d[i + 2] = b;
}

// W [Kdim, Ndim] row-major -> Wt fp16 hi/lo [Ndim, Kdim]
__global__ __launch_bounds__(256) void transsplit16(const float* __restrict__ W,
                                                    __half* __restrict__ thi,
                                                    __half* __restrict__ tlo,
                                                    int Kdim, int Ndim) {
    __shared__ float t[32][33];
    int n0 = blockIdx.x * 32, k0 = blockIdx.y * 32;
    int tx = threadIdx.x, ty = threadIdx.y;
#pragma unroll
    for (int j = 0; j < 32; j += 8)
        t[ty + j][tx] = W[(size_t)(k0 + ty + j) * Ndim + n0 + tx];
    __syncthreads();
#pragma unroll
    for (int j = 0; j < 32; j += 8) {
        float v = t[tx][ty + j];
        __half h = __float2half_rn(v);
        size_t o = (size_t)(n0 + ty + j) * Kdim + k0 + tx;
        thi[o] = h;
        tlo[o] = __float2half_rn(v - __half2float(h));
    }
}

__global__ __launch_bounds__(256) void pack_bias(const float* __restrict__ adj,
                                                 const int* __restrict__ ety,
                                                 uint32_t* __restrict__ out) {
    size_t i = ((size_t)blockIdx.x * 256 + threadIdx.x) * 4;
    float4 a = *(const float4*)(adj + i);
    int4 t = *(const int4*)(ety + i);
    uint4 r;
    r.x = ((uint32_t)t.x << 16) | (uint32_t)__bfloat16_as_ushort(__float2bfloat16(a.x));
    r.y = ((uint32_t)t.y << 16) | (uint32_t)__bfloat16_as_ushort(__float2bfloat16(a.y));
    r.z = ((uint32_t)t.z << 16) | (uint32_t)__bfloat16_as_ushort(__float2bfloat16(a.z));
    r.w = ((uint32_t)t.w << 16) | (uint32_t)__bfloat16_as_ushort(__float2bfloat16(a.w));
    *(uint4*)(out + i) = r;
}

// ---------------------------------------------------------------------------
// fp16 GEMM, 2 MMAs/fragment: C = A(fp16) @ (Bhi+Blo)(fp16)^T.
// 128x128 tile, 8 warps (4x2), K-chunk 32, LDG-prefetch double buffer.
// mode 0: fp32 Cout. mode 1: QKV epilogue -> Q/K bf16 hi/lo (Q *0.125),
//   V fp16 hi/lo [b,h,d,t] key-permuted.
// NOTE: dynamic smem must cover BOTH the mainloop (2*BUF_B = 61440) and the
// V-epilogue float transpose (128*132*4 = 67584) -> request 69632.
// ---------------------------------------------------------------------------
#define KC 32
#define LDP 40
#define TILE_B (128 * LDP * 2)          // 10240
#define BUF_B  (3 * TILE_B)             // A, Bhi, Blo
#define SHM_GEMM 69632

__global__ __launch_bounds__(256)
void mma_gemm(const __half* __restrict__ A,
              const __half* __restrict__ Bhi, const __half* __restrict__ Blo,
              int Ncols, float* __restrict__ Cout, int mode) {
    extern __shared__ char smem[];
    uint32_t sb = smem_u32(smem);
    int tid = threadIdx.x, wid = tid >> 5, lane = tid & 31;
    int wm = wid & 3, wn = wid >> 2;
    int m0 = blockIdx.y * 128, n0 = blockIdx.x * 128;

    int r_ld  = tid >> 2;
    int c8_ld = (tid & 3) * 8;
    const __half* srcs[3] = {
        A + (size_t)m0 * GK, Bhi + (size_t)n0 * GK, Blo + (size_t)n0 * GK };

    uint32_t a_off = (uint32_t)((wm * 32 + (lane & 15)) * LDP + (lane >> 4) * 8) * 2;
    uint32_t b_off = (uint32_t)((wn * 64 + (lane & 7) + (lane >> 4) * 8) * LDP
                                + ((lane >> 3) & 1) * 8) * 2;

    float acc[2][8][4];
#pragma unroll
    for (int i = 0; i < 2; i++)
#pragma unroll
        for (int j = 0; j < 8; j++)
#pragma unroll
            for (int k = 0; k < 4; k++) acc[i][j][k] = 0.f;

    uint4 pf[3][2];
#pragma unroll
    for (int t = 0; t < 3; t++)
#pragma unroll
        for (int i = 0; i < 2; i++)
            pf[t][i] = *(const uint4*)(srcs[t] + (size_t)(r_ld + i * 64) * GK + c8_ld);
    {
        char* base = smem;
#pragma unroll
        for (int t = 0; t < 3; t++)
#pragma unroll
            for (int i = 0; i < 2; i++)
                *(uint4*)(base + t * TILE_B + ((r_ld + i * 64) * LDP + c8_ld) * 2) = pf[t][i];
    }
    __syncthreads();

    const int NCH = GK / KC;
    for (int kc = 0; kc < NCH; kc++) {
        int buf = kc & 1;
        if (kc + 1 < NCH) {
            size_t go = (size_t)(kc + 1) * KC;
#pragma unroll
            for (int t = 0; t < 3; t++)
#pragma unroll
                for (int i = 0; i < 2; i++)
                    pf[t][i] = *(const uint4*)(srcs[t] + (size_t)(r_ld + i * 64) * GK + go + c8_ld);
        }
        uint32_t sA  = sb + buf * BUF_B + a_off;
        uint32_t sBh = sb + buf * BUF_B + TILE_B + b_off;
        uint32_t sBl = sBh + TILE_B;
#pragma unroll
        for (int ks = 0; ks < 2; ks++) {
            uint32_t kb = (uint32_t)(ks * 16) * 2;
            uint32_t ah[2][4];
#pragma unroll
            for (int tm = 0; tm < 2; tm++) {
                uint32_t ro = (uint32_t)(tm * 16 * LDP) * 2;
                ldsm4(ah[tm], sA + ro + kb);
            }
#pragma unroll
            for (int pr = 0; pr < 4; pr++) {
                uint32_t po = (uint32_t)(pr * 16 * LDP) * 2;
                uint32_t bh[4], bl[4];
                ldsm4(bh, sBh + po + kb);
                ldsm4(bl, sBl + po + kb);
#pragma unroll
                for (int hf = 0; hf < 2; hf++) {
                    int tn = pr * 2 + hf;
#pragma unroll
                    for (int tm = 0; tm < 2; tm++) {
                        mma16816h(acc[tm][tn], ah[tm], bh + hf * 2);
                        mma16816h(acc[tm][tn], ah[tm], bl + hf * 2);
                    }
                }
            }
        }
        if (kc + 1 < NCH) {
            char* base = smem + (1 - buf) * BUF_B;
#pragma unroll
            for (int t = 0; t < 3; t++)
#pragma unroll
                for (int i = 0; i < 2; i++)
                    *(uint4*)(base + t * TILE_B + ((r_ld + i * 64) * LDP + c8_ld) * 2) = pf[t][i];
            __syncthreads();
        }
    }

    int rbase = m0 + wm * 32 + (lane >> 2);
    int cbase = n0 + wn * 64 + (lane & 3) * 2;

    if (mode == 0) {
#pragma unroll
        for (int tm = 0; tm < 2; tm++)
#pragma unroll
            for (int tn = 0; tn < 8; tn++)
#pragma unroll
                for (int half = 0; half < 2; half++) {
                    int m = rbase + tm * 16 + half * 8;
                    *(float2*)&Cout[(size_t)m * Ncols + cbase + tn * 8] =
                        make_float2(acc[tm][tn][half * 2], acc[tm][tn][half * 2 + 1]);
                }
        return;
    }

    int which = n0 >> 10;
    if (which < 2) {
        float sc = (which == 0) ? 0.125f : 1.0f;
        __nv_bfloat16* dh = which ? g_khi : g_qhi;
        __nv_bfloat16* dl = which ? g_klo : g_qlo;
#pragma unroll
        for (int tm = 0; tm < 2; tm++)
#pragma unroll
            for (int tn = 0; tn < 8; tn++)
#pragma unroll
                for (int half = 0; half < 2; half++) {
                    int m = rbase + tm * 16 + half * 8;
                    int n = cbase + tn * 8;
                    int h = (n & 1023) >> 6, d = n & 63;
                    int bI = m >> 11, t = m & 2047;
                    size_t ix = ((size_t)(bI * Hh + h) * Tt + t) * HDd + d;
                    uint32_t uh, ul;
                    pk2(acc[tm][tn][half * 2] * sc, acc[tm][tn][half * 2 + 1] * sc, uh, ul);
                    *(uint32_t*)&dh[ix] = uh;
                    *(uint32_t*)&dl[ix] = ul;
                }
    } else {
        // V: transpose via smem (float [128][132] = 67584 B <= SHM_GEMM),
        // store fp16 hi/lo [b,h,d,t] key-permuted
        float* buf = (float*)smem;
        __syncthreads();
#pragma unroll
        for (int tm = 0; tm < 2; tm++)
#pragma unroll
            for (int tn = 0; tn < 8; tn++)
#pragma unroll
                for (int half = 0; half < 2; half++) {
                    int nl = wn * 64 + tn * 8 + (lane & 3) * 2;
                    int ml = wm * 32 + (lane >> 2) + tm * 16 + half * 8;
                    buf[nl * 132 + ml]       = acc[tm][tn][half * 2];
                    buf[(nl + 1) * 132 + ml] = acc[tm][tn][half * 2 + 1];
                }
        __syncthreads();
        int nl = tid >> 1, mh = (tid & 1) * 64;
        int n = n0 + nl;
        int h = (n & 1023) >> 6, d = n & 63;
        int bI = m0 >> 11, t0 = (m0 & 2047) + mh;
        size_t base = ((size_t)(bI * Hh + h) * HDd + d) * Tt + t0;
#pragma unroll
        for (int g = 0; g < 8; g++) {
            __half hi8[8], lo8[8];
#pragma unroll
            for (int e = 0; e < 8; e++) {
                int c = g * 8 + e;
                int src = 16 * ((c >> 1) & 3) + 2 * (c >> 3) + (c & 1);
                float f = buf[nl * 132 + mh + src];
                hi8[e] = __float2half_rn(f);
                lo8[e] = __float2half_rn(f - __half2float(hi8[e]));
            }
            *(uint4*)&g_vhi[base + g * 8] = *(uint4*)hi8;
            *(uint4*)&g_vlo[base + g * 8] = *(uint4*)lo8;
        }
    }
}

// ---------------------------------------------------------------------------
// Flash attention: QK^T = bf16 3-MMA split (unchanged accuracy path);
// PV = fp16 P-single x V-split (2 MMAs). cp.async KV, LPT, pipelined bias.
// ---------------------------------------------------------------------------
#define LQ 72
#define QB (128 * LQ * 2)
#define TB (64 * LQ * 2)
#define OKV (2 * QB)

__global__ __launch_bounds__(256, 2) void attn_mma(
    const uint32_t* __restrict__ pk, const float* __restrict__ adj_bias,
    const float* __restrict__ edge_table) {
    extern __shared__ char sm[];
    uint32_t sB = smem_u32(sm);
    float* ets = (float*)(sm + OKV + 8 * TB);

    int tid = threadIdx.x, w = tid >> 5, lane = tid & 31;
    int qt = (int)(gridDim.x - 1 - blockIdx.x);
    int h = blockIdx.y, b = blockIdx.z;
    int q0 = qt * 128, qw = q0 + 16 * w;
    float bco = adj_bias[h];
    if (tid < NEe) ets[tid] = edge_table[tid * Hh + h];

    {   // Q tile (pre-scaled bf16 hi/lo)
        const __nv_bfloat16* qh = g_qhi + ((size_t)(b * Hh + h) * Tt + q0) * HDd;
        const __nv_bfloat16* ql = g_qlo + ((size_t)(b * Hh + h) * Tt + q0) * HDd;
        __nv_bfloat16* sQh = (__nv_bfloat16*)sm;
        __nv_bfloat16* sQl = sQh + 128 * LQ;
        int r = tid >> 1, cg = (tid & 1) * 32;
#pragma unroll
        for (int u = 0; u < 4; u++) {
            *(uint4*)&sQh[r * LQ + cg + u * 8] = *(const uint4*)&qh[(size_t)r * 64 + cg + u * 8];
            *(uint4*)&sQl[r * LQ + cg + u * 8] = *(const uint4*)&ql[(size_t)r * 64 + cg + u * 8];
        }
    }

    int c = tid >> 2, dg = (tid & 3) * 16;
    int gkp = 16 * ((c >> 1) & 3) + 2 * (c >> 3) + (c & 1);
    uint32_t krow = (uint32_t)(c * LQ + dg) * 2;
    const __nv_bfloat16* bkh = g_khi + ((size_t)(b * Hh + h) * Tt + gkp) * HDd + dg;
    const __nv_bfloat16* bkl = g_klo + ((size_t)(b * Hh + h) * Tt + gkp) * HDd + dg;
    const __half* bvh = g_vhi + ((size_t)(b * Hh + h) * HDd + c) * Tt + dg;
    const __half* bvl = g_vlo + ((size_t)(b * Hh + h) * HDd + c) * Tt + dg;

#define LOADKV(jt, bf) do {                                                     \
    int _k0 = (jt) * 64;                                                        \
    uint32_t _bs = sB + OKV + (bf) * 4 * TB;                                    \
    cpa16(_bs + krow,               bkh + (size_t)_k0 * HDd);                   \
    cpa16(_bs + krow + 16,          bkh + (size_t)_k0 * HDd + 8);               \
    cpa16(_bs + TB + krow,          bkl + (size_t)_k0 * HDd);                   \
    cpa16(_bs + TB + krow + 16,     bkl + (size_t)_k0 * HDd + 8);               \
    cpa16(_bs + 2 * TB + krow,      bvh + _k0);                                 \
    cpa16(_bs + 2 * TB + krow + 16, bvh + _k0 + 8);                             \
    cpa16(_bs + 3 * TB + krow,      bvl + _k0);                                 \
    cpa16(_bs + 3 * TB + krow + 16, bvl + _k0 + 8);                             \
    CPC();                                                                      \
} while (0)

    float o[8][4];
#pragma unroll
    for (int i = 0; i < 8; i++)
#pragma unroll
        for (int j = 0; j < 4; j++) o[i][j] = 0.f;
    float m0r = -1e30f, m1r = -1e30f, l0r = 0.f, l1r = 0.f;

    LOADKV(0, 0);

    int a = lane & 3, grp = lane >> 2;
    const uint32_t* pkb = pk + ((size_t)b * Tt + qw + grp) * Tt + 16 * a;

    int nkt = 2 * qt + 2;
    for (int jt = 0; jt < nkt; jt++) {
        int k0 = jt * 64;
        int buf = jt & 1;
        CPW0();
        __syncthreads();
        if (jt + 1 < nkt) LOADKV(jt + 1, buf ^ 1);

        if (k0 > qw + 15) continue;

        uint32_t oKh = OKV + buf * 4 * TB, oKl = oKh + TB, oVh = oKl + TB, oVl = oVh + TB;

        uint4 u0[4];
        {
            const uint4* bp0 = (const uint4*)(pkb + k0);
            u0[0] = bp0[0]; u0[1] = bp0[1]; u0[2] = bp0[2]; u0[3] = bp0[3];
        }

        float s[8][4];
#pragma unroll
        for (int i = 0; i < 8; i++)
#pragma unroll
            for (int j = 0; j < 4; j++) s[i][j] = 0.f;

        uint32_t acol = (uint32_t)((lane >> 4) * 8) * 2;
        uint32_t arow = (uint32_t)((16 * w + (lane & 15)) * LQ) * 2;
        uint32_t bro  = (uint32_t)(((lane & 7) + (lane >> 4) * 8) * LQ) * 2;
        uint32_t bco2 = (uint32_t)(((lane >> 3) & 1) * 8) * 2;
#pragma unroll
        for (int ck = 0; ck < 4; ck++) {
            uint32_t kb = (uint32_t)(ck * 16) * 2;
            uint32_t aqh[4], aql[4];
            ldsm4(aqh, sB + arow + acol + kb);
            ldsm4(aql, sB + QB + arow + acol + kb);
#pragma unroll
            for (int pr = 0; pr < 4; pr++) {
                uint32_t ro = (uint32_t)(pr * 16 * LQ) * 2;
                uint32_t bh[4], bl[4];
                ldsm4(bh, sB + oKh + bro + ro + bco2 + kb);
                ldsm4(bl, sB + oKl + bro + ro + bco2 + kb);
#pragma unroll
                for (int hf = 0; hf < 2; hf++) {
                    int tn = pr * 2 + hf;
                    mma16816(s[tn], aqh, bh + hf * 2);
                    mma16816(s[tn], aqh, bl + hf * 2);
                    mma16816(s[tn], aql, bh + hf * 2);
                }
            }
        }

        uint4 u1[4];
        {
            const uint4* bp1 = (const uint4*)(pkb + 8 * Tt + k0);
            u1[0] = bp1[0]; u1[1] = bp1[1]; u1[2] = bp1[2]; u1[3] = bp1[3];
        }

        bool mm = (k0 + 63 > qw);
        float alpha0, alpha1;
#pragma unroll
        for (int half = 0; half < 2; half++) {
            int q = qw + grp + 8 * half;
            const uint32_t* ub = (const uint32_t*)(half ? u1 : u0);
            float mx = -1e30f;
#pragma unroll
            for (int nt = 0; nt < 8; nt++)
#pragma unroll
                for (int e = 0; e < 2; e++) {
                    int kk = 2 * nt + e;
                    uint32_t pv = ub[kk];
                    float sv = s[nt][half * 2 + e] + bco * __uint_as_float(pv << 16)
                               + ets[pv >> 16];
                    if (mm && (k0 + 16 * a + kk > q)) sv = -1e30f;
                    s[nt][half * 2 + e] = sv;
                    mx = fmaxf(mx, sv);
                }
            mx = fmaxf(mx, __shfl_xor_sync(0xffffffffu, mx, 1));
            mx = fmaxf(mx, __shfl_xor_sync(0xffffffffu, mx, 2));
            float mold = half ? m1r : m0r;
            float mnew = fmaxf(mold, mx);
            float sum = 0.f;
#pragma unroll
            for (int nt = 0; nt < 8; nt++)
#pragma unroll
                for (int e = 0; e < 2; e++) {
                    float p = __expf(s[nt][half * 2 + e] - mnew);
                    s[nt][half * 2 + e] = p;
                    sum += p;
                }
            sum += __shfl_xor_sync(0xffffffffu, sum, 1);
            sum += __shfl_xor_sync(0xffffffffu, sum, 2);
            float al = __expf(mold - mnew);
            if (half == 0) { m0r = mnew; l0r = l0r * al + sum; alpha0 = al; }
            else           { m1r = mnew; l1r = l1r * al + sum; alpha1 = al; }
        }

#pragma unroll
        for (int nt = 0; nt < 8; nt++) {
            o[nt][0] *= alpha0; o[nt][1] *= alpha0;
            o[nt][2] *= alpha1; o[nt][3] *= alpha1;
        }
        // PV: P single fp16, V fp16 hi/lo -> 2 MMAs per fragment
#pragma unroll
        for (int j = 0; j < 4; j++) {
            uint32_t ph[4];
            ph[0] = h2u(s[2*j][0],   s[2*j][1]);
            ph[1] = h2u(s[2*j][2],   s[2*j][3]);
            ph[2] = h2u(s[2*j+1][0], s[2*j+1][1]);
            ph[3] = h2u(s[2*j+1][2], s[2*j+1][3]);
            uint32_t kb = (uint32_t)(j * 16) * 2;
#pragma unroll
            for (int pr = 0; pr < 4; pr++) {
                uint32_t ro = (uint32_t)(pr * 16 * LQ) * 2;
                uint32_t vh[4], vl[4];
                ldsm4(vh, sB + oVh + bro + ro + bco2 + kb);
                ldsm4(vl, sB + oVl + bro + ro + bco2 + kb);
#pragma unroll
                for (int hf = 0; hf < 2; hf++) {
                    int tn = pr * 2 + hf;
                    mma16816h(o[tn], ph, vh + hf * 2);
                    mma16816h(o[tn], ph, vl + hf * 2);
                }
            }
        }
    }

    // finalize -> single fp16 ao for proj GEMM
    float il0 = 1.f / l0r, il1 = 1.f / l1r;
    size_t ix = ((size_t)b * Tt + qw + grp) * Dd + h * 64 + a * 2;
#pragma unroll
    for (int nt = 0; nt < 8; nt++) {
        *(uint32_t*)&g_ao16[ix + nt * 8]          = h2u(o[nt][0] * il0, o[nt][1] * il0);
        *(uint32_t*)&g_ao16[ix + 8 * Dd + nt * 8] = h2u(o[nt][2] * il1, o[nt][3] * il1);
    }
}

// ---------------------------------------------------------------------------
extern "C" void kernel_launch(void* const* d_in, const int* in_sizes, int n_in,
                              void* d_out, int out_size) {
    const float* x     = (const float*)d_in[0];
    const float* gadj  = (const float*)d_in[1];
    const int*   etyp  = (const int*)d_in[2];
    const float* wqkv  = (const float*)d_in[3];
    const float* wproj = (const float*)d_in[4];
    const float* abias = (const float*)d_in[5];
    const float* etab  = (const float*)d_in[6];
    float* out = (float*)d_out;

    __half *x16, *wq16h, *wq16l, *wp16h, *wp16l, *ao16;
    uint32_t* packp;
    cudaGetSymbolAddress((void**)&x16,   g_x16);
    cudaGetSymbolAddress((void**)&wq16h, g_wq16h); cudaGetSymbolAddress((void**)&wq16l, g_wq16l);
    cudaGetSymbolAddress((void**)&wp16h, g_wp16h); cudaGetSymbolAddress((void**)&wp16l, g_wp16l);
    cudaGetSymbolAddress((void**)&ao16,  g_ao16);
    cudaGetSymbolAddress((void**)&packp, g_pack);

    cudaFuncSetAttribute(mma_gemm, cudaFuncAttributeMaxDynamicSharedMemorySize, SHM_GEMM);
    const int SMA = OKV + 8 * TB + 128;               // 110720
    cudaFuncSetAttribute(attn_mma, cudaFuncAttributeMaxDynamicSharedMemorySize, SMA);

    cvt16<<<(Bb * Tt * Dd) / 1024, 256>>>(x, x16);
    transsplit16<<<dim3(3 * Dd / 32, Dd / 32), dim3(32, 8)>>>(wqkv, wq16h, wq16l, Dd, 3 * Dd);
    transsplit16<<<dim3(Dd / 32, Dd / 32), dim3(32, 8)>>>(wproj, wp16h, wp16l, Dd, Dd);
    pack_bias<<<(int)(((size_t)Bb * Tt * Tt) / 1024), 256>>>(gadj, etyp, packp);

    mma_gemm<<<dim3(3 * Dd / 128, Bb * Tt / 128), 256, SHM_GEMM>>>(
        x16, wq16h, wq16l, 3 * Dd, nullptr, 1);

    attn_mma<<<dim3(Tt / 128, Hh, Bb), 256, SMA>>>(packp, abias, etab);

    mma_gemm<<<dim3(Dd / 128, Bb * Tt / 128), 256, SHM_GEMM>>>(
        ao16, wp16h, wp16l, Dd, out, 0);
}

// round 13
// speedup vs baseline: 2.9281x; 1.0818x over previous
#include <cuda_runtime.h>
#include <cuda_bf16.h>
#include <cuda_fp16.h>
#include <math.h>
#include <cstdint>

#define Bb 2
#define Tt 2048
#define Dd 1024
#define Hh 16
#define HDd 64
#define NEe 17
#define GK 1024

// ---------------- scratch globals ----------------
__device__ __half g_x16[Bb*Tt*Dd];                                   // x single fp16
__device__ __half g_wq16h[3*Dd*Dd], g_wq16l[3*Dd*Dd];                // Wqkv^T fp16 hi/lo
__device__ __half g_wp16h[Dd*Dd],   g_wp16l[Dd*Dd];                  // Wproj^T fp16 hi/lo
__device__ __half g_ao16[Bb*Tt*Dd];                                  // attn out single fp16
__device__ __half g_q16[Bb*Hh*Tt*HDd];                               // [b,h,t,d] *0.125 single
__device__ __half g_k16h[Bb*Hh*Tt*HDd], g_k16l[Bb*Hh*Tt*HDd];        // [b,h,t,d] fp16 split
__device__ __half g_v16[Bb*Hh*Tt*HDd];                               // [b,h,d,t] single, key-permuted
__device__ uint32_t g_pack[(size_t)Bb*Tt*Tt];

// ---------------- helpers ----------------
__device__ __forceinline__ uint32_t smem_u32(const void* p) {
    uint32_t a;
    asm("{ .reg .u64 t; cvta.to.shared.u64 t, %1; cvt.u32.u64 %0, t; }" : "=r"(a) : "l"(p));
    return a;
}
__device__ __forceinline__ void ldsm4(uint32_t* r, uint32_t addr) {
    asm volatile("ldmatrix.sync.aligned.m8n8.x4.shared.b16 {%0,%1,%2,%3}, [%4];"
        : "=r"(r[0]), "=r"(r[1]), "=r"(r[2]), "=r"(r[3]) : "r"(addr));
}
__device__ __forceinline__ void mma16816h(float* c, const uint32_t* a, const uint32_t* b) {
    asm volatile("mma.sync.aligned.m16n8k16.row.col.f32.f16.f16.f32 "
        "{%0,%1,%2,%3}, {%4,%5,%6,%7}, {%8,%9}, {%0,%1,%2,%3};"
        : "+f"(c[0]), "+f"(c[1]), "+f"(c[2]), "+f"(c[3])
        : "r"(a[0]), "r"(a[1]), "r"(a[2]), "r"(a[3]), "r"(b[0]), "r"(b[1]));
}
__device__ __forceinline__ uint32_t h2u(float a, float b) {
    __half2 v = __floats2half2_rn(a, b);
    return *(uint32_t*)&v;
}
__device__ __forceinline__ void pk2h(float a, float b, uint32_t& hi, uint32_t& lo) {
    __half ha = __float2half_rn(a), hb = __float2half_rn(b);
    __half2 hh(ha, hb); hi = *(uint32_t*)&hh;
    __half2 ll(__float2half_rn(a - __half2float(ha)),
               __float2half_rn(b - __half2float(hb)));
    lo = *(uint32_t*)&ll;
}
__device__ __forceinline__ void cpa16(uint32_t s, const void* g) {
    asm volatile("cp.async.cg.shared.global [%0], [%1], 16;" :: "r"(s), "l"(g));
}
#define CPC()  asm volatile("cp.async.commit_group;" ::: "memory")
#define CPW0() asm volatile("cp.async.wait_group 0;" ::: "memory")

// ---------------- prep kernels ----------------
__global__ __launch_bounds__(256) void cvt16(const float* __restrict__ s,
                                             __half* __restrict__ d) {
    int i = (blockIdx.x * 256 + threadIdx.x) * 4;
    float4 v = *(const float4*)(s + i);
    *(__half2*)&d[i]     = __floats2half2_rn(v.x, v.y);
    *(__half2*)&d[i + 2] = __floats2half2_rn(v.z, v.w);
}

__global__ __launch_bounds__(256) void transsplit16(const float* __restrict__ W,
                                                    __half* __restrict__ thi,
                                                    __half* __restrict__ tlo,
                                                    int Kdim, int Ndim) {
    __shared__ float t[32][33];
    int n0 = blockIdx.x * 32, k0 = blockIdx.y * 32;
    int tx = threadIdx.x, ty = threadIdx.y;
#pragma unroll
    for (int j = 0; j < 32; j += 8)
        t[ty + j][tx] = W[(size_t)(k0 + ty + j) * Ndim + n0 + tx];
    __syncthreads();
#pragma unroll
    for (int j = 0; j < 32; j += 8) {
        float v = t[tx][ty + j];
        __half h = __float2half_rn(v);
        size_t o = (size_t)(n0 + ty + j) * Kdim + k0 + tx;
        thi[o] = h;
        tlo[o] = __float2half_rn(v - __half2float(h));
    }
}

__global__ __launch_bounds__(256) void pack_bias(const float* __restrict__ adj,
                                                 const int* __restrict__ ety,
                                                 uint32_t* __restrict__ out) {
    size_t i = ((size_t)blockIdx.x * 256 + threadIdx.x) * 4;
    float4 a = *(const float4*)(adj + i);
    int4 t = *(const int4*)(ety + i);
    uint4 r;
    r.x = ((uint32_t)t.x << 16) | (uint32_t)__bfloat16_as_ushort(__float2bfloat16(a.x));
    r.y = ((uint32_t)t.y << 16) | (uint32_t)__bfloat16_as_ushort(__float2bfloat16(a.y));
    r.z = ((uint32_t)t.z << 16) | (uint32_t)__bfloat16_as_ushort(__float2bfloat16(a.z));
    r.w = ((uint32_t)t.w << 16) | (uint32_t)__bfloat16_as_ushort(__float2bfloat16(a.w));
    *(uint4*)(out + i) = r;
}

// ---------------------------------------------------------------------------
// fp16 GEMM, 2 MMAs/fragment: C = A(fp16) @ (Bhi+Blo)(fp16)^T.
// mode 0: fp32 Cout. mode 1: QKV epilogue -> Q single fp16 (*0.125),
//   K fp16 hi/lo, V single fp16 [b,h,d,t] key-permuted.
// smem covers mainloop (61440) AND V-epilogue transpose (67584) -> 69632.
// ---------------------------------------------------------------------------
#define KC 32
#define LDP 40
#define TILE_B (128 * LDP * 2)          // 10240
#define BUF_B  (3 * TILE_B)
#define SHM_GEMM 69632

__global__ __launch_bounds__(256)
void mma_gemm(const __half* __restrict__ A,
              const __half* __restrict__ Bhi, const __half* __restrict__ Blo,
              int Ncols, float* __restrict__ Cout, int mode) {
    extern __shared__ char smem[];
    uint32_t sb = smem_u32(smem);
    int tid = threadIdx.x, wid = tid >> 5, lane = tid & 31;
    int wm = wid & 3, wn = wid >> 2;
    int m0 = blockIdx.y * 128, n0 = blockIdx.x * 128;

    int r_ld  = tid >> 2;
    int c8_ld = (tid & 3) * 8;
    const __half* srcs[3] = {
        A + (size_t)m0 * GK, Bhi + (size_t)n0 * GK, Blo + (size_t)n0 * GK };

    uint32_t a_off = (uint32_t)((wm * 32 + (lane & 15)) * LDP + (lane >> 4) * 8) * 2;
    uint32_t b_off = (uint32_t)((wn * 64 + (lane & 7) + (lane >> 4) * 8) * LDP
                                + ((lane >> 3) & 1) * 8) * 2;

    float acc[2][8][4];
#pragma unroll
    for (int i = 0; i < 2; i++)
#pragma unroll
        for (int j = 0; j < 8; j++)
#pragma unroll
            for (int k = 0; k < 4; k++) acc[i][j][k] = 0.f;

    uint4 pf[3][2];
#pragma unroll
    for (int t = 0; t < 3; t++)
#pragma unroll
        for (int i = 0; i < 2; i++)
            pf[t][i] = *(const uint4*)(srcs[t] + (size_t)(r_ld + i * 64) * GK + c8_ld);
    {
        char* base = smem;
#pragma unroll
        for (int t = 0; t < 3; t++)
#pragma unroll
            for (int i = 0; i < 2; i++)
                *(uint4*)(base + t * TILE_B + ((r_ld + i * 64) * LDP + c8_ld) * 2) = pf[t][i];
    }
    __syncthreads();

    const int NCH = GK / KC;
    for (int kc = 0; kc < NCH; kc++) {
        int buf = kc & 1;
        if (kc + 1 < NCH) {
            size_t go = (size_t)(kc + 1) * KC;
#pragma unroll
            for (int t = 0; t < 3; t++)
#pragma unroll
                for (int i = 0; i < 2; i++)
                    pf[t][i] = *(const uint4*)(srcs[t] + (size_t)(r_ld + i * 64) * GK + go + c8_ld);
        }
        uint32_t sA  = sb + buf * BUF_B + a_off;
        uint32_t sBh = sb + buf * BUF_B + TILE_B + b_off;
        uint32_t sBl = sBh + TILE_B;
#pragma unroll
        for (int ks = 0; ks < 2; ks++) {
            uint32_t kb = (uint32_t)(ks * 16) * 2;
            uint32_t ah[2][4];
#pragma unroll
            for (int tm = 0; tm < 2; tm++) {
                uint32_t ro = (uint32_t)(tm * 16 * LDP) * 2;
                ldsm4(ah[tm], sA + ro + kb);
            }
#pragma unroll
            for (int pr = 0; pr < 4; pr++) {
                uint32_t po = (uint32_t)(pr * 16 * LDP) * 2;
                uint32_t bh[4], bl[4];
                ldsm4(bh, sBh + po + kb);
                ldsm4(bl, sBl + po + kb);
#pragma unroll
                for (int hf = 0; hf < 2; hf++) {
                    int tn = pr * 2 + hf;
#pragma unroll
                    for (int tm = 0; tm < 2; tm++) {
                        mma16816h(acc[tm][tn], ah[tm], bh + hf * 2);
                        mma16816h(acc[tm][tn], ah[tm], bl + hf * 2);
                    }
                }
            }
        }
        if (kc + 1 < NCH) {
            char* base = smem + (1 - buf) * BUF_B;
#pragma unroll
            for (int t = 0; t < 3; t++)
#pragma unroll
                for (int i = 0; i < 2; i++)
                    *(uint4*)(base + t * TILE_B + ((r_ld + i * 64) * LDP + c8_ld) * 2) = pf[t][i];
            __syncthreads();
        }
    }

    int rbase = m0 + wm * 32 + (lane >> 2);
    int cbase = n0 + wn * 64 + (lane & 3) * 2;

    if (mode == 0) {
#pragma unroll
        for (int tm = 0; tm < 2; tm++)
#pragma unroll
            for (int tn = 0; tn < 8; tn++)
#pragma unroll
                for (int half = 0; half < 2; half++) {
                    int m = rbase + tm * 16 + half * 8;
                    *(float2*)&Cout[(size_t)m * Ncols + cbase + tn * 8] =
                        make_float2(acc[tm][tn][half * 2], acc[tm][tn][half * 2 + 1]);
                }
        return;
    }

    int which = n0 >> 10;
    if (which == 0) {
        // Q: single fp16, pre-scaled
#pragma unroll
        for (int tm = 0; tm < 2; tm++)
#pragma unroll
            for (int tn = 0; tn < 8; tn++)
#pragma unroll
                for (int half = 0; half < 2; half++) {
                    int m = rbase + tm * 16 + half * 8;
                    int n = cbase + tn * 8;
                    int h = (n & 1023) >> 6, d = n & 63;
                    int bI = m >> 11, t = m & 2047;
                    size_t ix = ((size_t)(bI * Hh + h) * Tt + t) * HDd + d;
                    *(uint32_t*)&g_q16[ix] =
                        h2u(acc[tm][tn][half * 2] * 0.125f, acc[tm][tn][half * 2 + 1] * 0.125f);
                }
    } else if (which == 1) {
        // K: fp16 hi/lo split
#pragma unroll
        for (int tm = 0; tm < 2; tm++)
#pragma unroll
            for (int tn = 0; tn < 8; tn++)
#pragma unroll
                for (int half = 0; half < 2; half++) {
                    int m = rbase + tm * 16 + half * 8;
                    int n = cbase + tn * 8;
                    int h = (n & 1023) >> 6, d = n & 63;
                    int bI = m >> 11, t = m & 2047;
                    size_t ix = ((size_t)(bI * Hh + h) * Tt + t) * HDd + d;
                    uint32_t uh, ul;
                    pk2h(acc[tm][tn][half * 2], acc[tm][tn][half * 2 + 1], uh, ul);
                    *(uint32_t*)&g_k16h[ix] = uh;
                    *(uint32_t*)&g_k16l[ix] = ul;
                }
    } else {
        // V: transpose via smem (float [128][132] <= SHM_GEMM),
        // store single fp16 [b,h,d,t] key-permuted
        float* buf = (float*)smem;
        __syncthreads();
#pragma unroll
        for (int tm = 0; tm < 2; tm++)
#pragma unroll
            for (int tn = 0; tn < 8; tn++)
#pragma unroll
                for (int half = 0; half < 2; half++) {
                    int nl = wn * 64 + tn * 8 + (lane & 3) * 2;
                    int ml = wm * 32 + (lane >> 2) + tm * 16 + half * 8;
                    buf[nl * 132 + ml]       = acc[tm][tn][half * 2];
                    buf[(nl + 1) * 132 + ml] = acc[tm][tn][half * 2 + 1];
                }
        __syncthreads();
        int nl = tid >> 1, mh = (tid & 1) * 64;
        int n = n0 + nl;
        int h = (n & 1023) >> 6, d = n & 63;
        int bI = m0 >> 11, t0 = (m0 & 2047) + mh;
        size_t base = ((size_t)(bI * Hh + h) * HDd + d) * Tt + t0;
#pragma unroll
        for (int g = 0; g < 8; g++) {
            __half v8[8];
#pragma unroll
            for (int e = 0; e < 8; e++) {
                int c = g * 8 + e;
                int src = 16 * ((c >> 1) & 3) + 2 * (c >> 3) + (c & 1);
                v8[e] = __float2half_rn(buf[nl * 132 + mh + src]);
            }
            *(uint4*)&g_v16[base + g * 8] = *(uint4*)v8;
        }
    }
}

// ---------------------------------------------------------------------------
// Flash attention: QK^T = Q(single) x K(split) = 2 MMAs; PV = P(single) x
// V(single) = 1 MMA. cp.async KV double-buffer, LPT, pipelined bias.
// ---------------------------------------------------------------------------
#define LQ 72
#define QB (128 * LQ * 2)
#define TB (64 * LQ * 2)
#define OKV QB                          // KV buffers start after single Q tile

__global__ __launch_bounds__(256, 2) void attn_mma(
    const uint32_t* __restrict__ pk, const float* __restrict__ adj_bias,
    const float* __restrict__ edge_table) {
    extern __shared__ char sm[];
    uint32_t sB = smem_u32(sm);
    float* ets = (float*)(sm + OKV + 6 * TB);

    int tid = threadIdx.x, w = tid >> 5, lane = tid & 31;
    int qt = (int)(gridDim.x - 1 - blockIdx.x);
    int h = blockIdx.y, b = blockIdx.z;
    int q0 = qt * 128, qw = q0 + 16 * w;
    float bco = adj_bias[h];
    if (tid < NEe) ets[tid] = edge_table[tid * Hh + h];

    {   // Q tile (single fp16, pre-scaled)
        const __half* qp = g_q16 + ((size_t)(b * Hh + h) * Tt + q0) * HDd;
        __half* sQ = (__half*)sm;
        int r = tid >> 1, cg = (tid & 1) * 32;
#pragma unroll
        for (int u = 0; u < 4; u++)
            *(uint4*)&sQ[r * LQ + cg + u * 8] = *(const uint4*)&qp[(size_t)r * 64 + cg + u * 8];
    }

    int c = tid >> 2, dg = (tid & 3) * 16;
    int gkp = 16 * ((c >> 1) & 3) + 2 * (c >> 3) + (c & 1);
    uint32_t krow = (uint32_t)(c * LQ + dg) * 2;
    const __half* bkh = g_k16h + ((size_t)(b * Hh + h) * Tt + gkp) * HDd + dg;
    const __half* bkl = g_k16l + ((size_t)(b * Hh + h) * Tt + gkp) * HDd + dg;
    const __half* bv  = g_v16  + ((size_t)(b * Hh + h) * HDd + c) * Tt + dg;

#define LOADKV(jt, bf) do {                                                     \
    int _k0 = (jt) * 64;                                                        \
    uint32_t _bs = sB + OKV + (bf) * 3 * TB;                                    \
    cpa16(_bs + krow,               bkh + (size_t)_k0 * HDd);                   \
    cpa16(_bs + krow + 16,          bkh + (size_t)_k0 * HDd + 8);               \
    cpa16(_bs + TB + krow,          bkl + (size_t)_k0 * HDd);                   \
    cpa16(_bs + TB + krow + 16,     bkl + (size_t)_k0 * HDd + 8);               \
    cpa16(_bs + 2 * TB + krow,      bv + _k0);                                  \
    cpa16(_bs + 2 * TB + krow + 16, bv + _k0 + 8);                              \
    CPC();                                                                      \
} while (0)

    float o[8][4];
#pragma unroll
    for (int i = 0; i < 8; i++)
#pragma unroll
        for (int j = 0; j < 4; j++) o[i][j] = 0.f;
    float m0r = -1e30f, m1r = -1e30f, l0r = 0.f, l1r = 0.f;

    LOADKV(0, 0);

    int a = lane & 3, grp = lane >> 2;
    const uint32_t* pkb = pk + ((size_t)b * Tt + qw + grp) * Tt + 16 * a;

    int nkt = 2 * qt + 2;
    for (int jt = 0; jt < nkt; jt++) {
        int k0 = jt * 64;
        int buf = jt & 1;
        CPW0();
        __syncthreads();
        if (jt + 1 < nkt) LOADKV(jt + 1, buf ^ 1);

        if (k0 > qw + 15) continue;

        uint32_t oKh = OKV + buf * 3 * TB, oKl = oKh + TB, oV = oKl + TB;

        uint4 u0[4];
        {
            const uint4* bp0 = (const uint4*)(pkb + k0);
            u0[0] = bp0[0]; u0[1] = bp0[1]; u0[2] = bp0[2]; u0[3] = bp0[3];
        }

        float s[8][4];
#pragma unroll
        for (int i = 0; i < 8; i++)
#pragma unroll
            for (int j = 0; j < 4; j++) s[i][j] = 0.f;

        uint32_t acol = (uint32_t)((lane >> 4) * 8) * 2;
        uint32_t arow = (uint32_t)((16 * w + (lane & 15)) * LQ) * 2;
        uint32_t bro  = (uint32_t)(((lane & 7) + (lane >> 4) * 8) * LQ) * 2;
        uint32_t bco2 = (uint32_t)(((lane >> 3) & 1) * 8) * 2;
#pragma unroll
        for (int ck = 0; ck < 4; ck++) {
            uint32_t kb = (uint32_t)(ck * 16) * 2;
            uint32_t aq[4];
            ldsm4(aq, sB + arow + acol + kb);
#pragma unroll
            for (int pr = 0; pr < 4; pr++) {
                uint32_t ro = (uint32_t)(pr * 16 * LQ) * 2;
                uint32_t bh[4], bl[4];
                ldsm4(bh, sB + oKh + bro + ro + bco2 + kb);
                ldsm4(bl, sB + oKl + bro + ro + bco2 + kb);
#pragma unroll
                for (int hf = 0; hf < 2; hf++) {
                    int tn = pr * 2 + hf;
                    mma16816h(s[tn], aq, bh + hf * 2);
                    mma16816h(s[tn], aq, bl + hf * 2);
                }
            }
        }

        uint4 u1[4];
        {
            const uint4* bp1 = (const uint4*)(pkb + 8 * Tt + k0);
            u1[0] = bp1[0]; u1[1] = bp1[1]; u1[2] = bp1[2]; u1[3] = bp1[3];
        }

        bool mm = (k0 + 63 > qw);
        float alpha0, alpha1;
#pragma unroll
        for (int half = 0; half < 2; half++) {
            int q = qw + grp + 8 * half;
            const uint32_t* ub = (const uint32_t*)(half ? u1 : u0);
            float mx = -1e30f;
#pragma unroll
            for (int nt = 0; nt < 8; nt++)
#pragma unroll
                for (int e = 0; e < 2; e++) {
                    int kk = 2 * nt + e;
                    uint32_t pv = ub[kk];
                    float sv = s[nt][half * 2 + e] + bco * __uint_as_float(pv << 16)
                               + ets[pv >> 16];
                    if (mm && (k0 + 16 * a + kk > q)) sv = -1e30f;
                    s[nt][half * 2 + e] = sv;
                    mx = fmaxf(mx, sv);
                }
            mx = fmaxf(mx, __shfl_xor_sync(0xffffffffu, mx, 1));
            mx = fmaxf(mx, __shfl_xor_sync(0xffffffffu, mx, 2));
            float mold = half ? m1r : m0r;
            float mnew = fmaxf(mold, mx);
            float sum = 0.f;
#pragma unroll
            for (int nt = 0; nt < 8; nt++)
#pragma unroll
                for (int e = 0; e < 2; e++) {
                    float p = __expf(s[nt][half * 2 + e] - mnew);
                    s[nt][half * 2 + e] = p;
                    sum += p;
                }
            sum += __shfl_xor_sync(0xffffffffu, sum, 1);
            sum += __shfl_xor_sync(0xffffffffu, sum, 2);
            float al = __expf(mold - mnew);
            if (half == 0) { m0r = mnew; l0r = l0r * al + sum; alpha0 = al; }
            else           { m1r = mnew; l1r = l1r * al + sum; alpha1 = al; }
        }

#pragma unroll
        for (int nt = 0; nt < 8; nt++) {
            o[nt][0] *= alpha0; o[nt][1] *= alpha0;
            o[nt][2] *= alpha1; o[nt][3] *= alpha1;
        }
        // PV: P single x V single -> 1 MMA per fragment
#pragma unroll
        for (int j = 0; j < 4; j++) {
            uint32_t ph[4];
            ph[0] = h2u(s[2*j][0],   s[2*j][1]);
            ph[1] = h2u(s[2*j][2],   s[2*j][3]);
            ph[2] = h2u(s[2*j+1][0], s[2*j+1][1]);
            ph[3] = h2u(s[2*j+1][2], s[2*j+1][3]);
            uint32_t kb = (uint32_t)(j * 16) * 2;
#pragma unroll
            for (int pr = 0; pr < 4; pr++) {
                uint32_t ro = (uint32_t)(pr * 16 * LQ) * 2;
                uint32_t vv[4];
                ldsm4(vv, sB + oV + bro + ro + bco2 + kb);
#pragma unroll
                for (int hf = 0; hf < 2; hf++)
                    mma16816h(o[pr * 2 + hf], ph, vv + hf * 2);
            }
        }
    }

    // finalize -> single fp16 ao for proj GEMM
    float il0 = 1.f / l0r, il1 = 1.f / l1r;
    size_t ix = ((size_t)b * Tt + qw + grp) * Dd + h * 64 + a * 2;
#pragma unroll
    for (int nt = 0; nt < 8; nt++) {
        *(uint32_t*)&g_ao16[ix + nt * 8]          = h2u(o[nt][0] * il0, o[nt][1] * il0);
        *(uint32_t*)&g_ao16[ix + 8 * Dd + nt * 8] = h2u(o[nt][2] * il1, o[nt][3] * il1);
    }
}

// ---------------------------------------------------------------------------
extern "C" void kernel_launch(void* const* d_in, const int* in_sizes, int n_in,
                              void* d_out, int out_size) {
    const float* x     = (const float*)d_in[0];
    const float* gadj  = (const float*)d_in[1];
    const int*   etyp  = (const int*)d_in[2];
    const float* wqkv  = (const float*)d_in[3];
    const float* wproj = (const float*)d_in[4];
    const float* abias = (const float*)d_in[5];
    const float* etab  = (const float*)d_in[6];
    float* out = (float*)d_out;

    __half *x16, *wq16h, *wq16l, *wp16h, *wp16l, *ao16;
    uint32_t* packp;
    cudaGetSymbolAddress((void**)&x16,   g_x16);
    cudaGetSymbolAddress((void**)&wq16h, g_wq16h); cudaGetSymbolAddress((void**)&wq16l, g_wq16l);
    cudaGetSymbolAddress((void**)&wp16h, g_wp16h); cudaGetSymbolAddress((void**)&wp16l, g_wp16l);
    cudaGetSymbolAddress((void**)&ao16,  g_ao16);
    cudaGetSymbolAddress((void**)&packp, g_pack);

    cudaFuncSetAttribute(mma_gemm, cudaFuncAttributeMaxDynamicSharedMemorySize, SHM_GEMM);
    const int SMA = OKV + 6 * TB + 128;   // 18432 + 55296 + 128 = 73856
    cudaFuncSetAttribute(attn_mma, cudaFuncAttributeMaxDynamicSharedMemorySize, SMA);

    cvt16<<<(Bb * Tt * Dd) / 1024, 256>>>(x, x16);
    transsplit16<<<dim3(3 * Dd / 32, Dd / 32), dim3(32, 8)>>>(wqkv, wq16h, wq16l, Dd, 3 * Dd);
    transsplit16<<<dim3(Dd / 32, Dd / 32), dim3(32, 8)>>>(wproj, wp16h, wp16l, Dd, Dd);
    pack_bias<<<(int)(((size_t)Bb * Tt * Tt) / 1024), 256>>>(gadj, etyp, packp);

    mma_gemm<<<dim3(3 * Dd / 128, Bb * Tt / 128), 256, SHM_GEMM>>>(
        x16, wq16h, wq16l, 3 * Dd, nullptr, 1);

    attn_mma<<<dim3(Tt / 128, Hh, Bb), 256, SMA>>>(packp, abias, etab);

    mma_gemm<<<dim3(Dd / 128, Bb * Tt / 128), 256, SHM_GEMM>>>(
        ao16, wp16h, wp16l, Dd, out, 0);
}

// round 14
// speedup vs baseline: 4.0728x; 1.3910x over previous
#include <cuda_runtime.h>
#include <cuda_bf16.h>
#include <cuda_fp16.h>
#include <math.h>
#include <cstdint>

#define Bb 2
#define Tt 2048
#define Dd 1024
#define Hh 16
#define HDd 64
#define NEe 17
#define GK 1024

// ---------------- scratch globals ----------------
__device__ __half g_x16[Bb*Tt*Dd];                                   // x single fp16
__device__ __half g_wq16[3*Dd*Dd];                                   // Wqkv^T fp16 single
__device__ __half g_wp16[Dd*Dd];                                     // Wproj^T fp16 single
__device__ __half g_ao16[Bb*Tt*Dd];                                  // attn out single fp16
__device__ __half g_q16[Bb*Hh*Tt*HDd];                               // [b,h,t,d] *0.125 single
__device__ __half g_k16[Bb*Hh*Tt*HDd];                               // [b,h,t,d] single
__device__ __half g_v16[Bb*Hh*Tt*HDd];                               // [b,h,d,t] single, key-permuted
__device__ uint32_t g_pack[(size_t)Bb*Tt*Tt];

// ---------------- helpers ----------------
__device__ __forceinline__ uint32_t smem_u32(const void* p) {
    uint32_t a;
    asm("{ .reg .u64 t; cvta.to.shared.u64 t, %1; cvt.u32.u64 %0, t; }" : "=r"(a) : "l"(p));
    return a;
}
__device__ __forceinline__ void ldsm4(uint32_t* r, uint32_t addr) {
    asm volatile("ldmatrix.sync.aligned.m8n8.x4.shared.b16 {%0,%1,%2,%3}, [%4];"
        : "=r"(r[0]), "=r"(r[1]), "=r"(r[2]), "=r"(r[3]) : "r"(addr));
}
__device__ __forceinline__ void mma16816h(float* c, const uint32_t* a, const uint32_t* b) {
    asm volatile("mma.sync.aligned.m16n8k16.row.col.f32.f16.f16.f32 "
        "{%0,%1,%2,%3}, {%4,%5,%6,%7}, {%8,%9}, {%0,%1,%2,%3};"
        : "+f"(c[0]), "+f"(c[1]), "+f"(c[2]), "+f"(c[3])
        : "r"(a[0]), "r"(a[1]), "r"(a[2]), "r"(a[3]), "r"(b[0]), "r"(b[1]));
}
__device__ __forceinline__ uint32_t h2u(float a, float b) {
    __half2 v = __floats2half2_rn(a, b);
    return *(uint32_t*)&v;
}
__device__ __forceinline__ void cpa16(uint32_t s, const void* g) {
    asm volatile("cp.async.cg.shared.global [%0], [%1], 16;" :: "r"(s), "l"(g));
}
#define CPC()  asm volatile("cp.async.commit_group;" ::: "memory")
#define CPW0() asm volatile("cp.async.wait_group 0;" ::: "memory")

// ---------------- prep kernels ----------------
__global__ __launch_bounds__(256) void cvt16(const float* __restrict__ s,
                                             __half* __restrict__ d) {
    int i = (blockIdx.x * 256 + threadIdx.x) * 4;
    float4 v = *(const float4*)(s + i);
    *(__half2*)&d[i]     = __floats2half2_rn(v.x, v.y);
    *(__half2*)&d[i + 2] = __floats2half2_rn(v.z, v.w);
}

// W [Kdim, Ndim] row-major -> Wt fp16 single [Ndim, Kdim]
__global__ __launch_bounds__(256) void transcvt16(const float* __restrict__ W,
                                                  __half* __restrict__ tw,
                                                  int Kdim, int Ndim) {
    __shared__ float t[32][33];
    int n0 = blockIdx.x * 32, k0 = blockIdx.y * 32;
    int tx = threadIdx.x, ty = threadIdx.y;
#pragma unroll
    for (int j = 0; j < 32; j += 8)
        t[ty + j][tx] = W[(size_t)(k0 + ty + j) * Ndim + n0 + tx];
    __syncthreads();
#pragma unroll
    for (int j = 0; j < 32; j += 8)
        tw[(size_t)(n0 + ty + j) * Kdim + k0 + tx] = __float2half_rn(t[tx][ty + j]);
}

__global__ __launch_bounds__(256) void pack_bias(const float* __restrict__ adj,
                                                 const int* __restrict__ ety,
                                                 uint32_t* __restrict__ out) {
    size_t i = ((size_t)blockIdx.x * 256 + threadIdx.x) * 4;
    float4 a = *(const float4*)(adj + i);
    int4 t = *(const int4*)(ety + i);
    uint4 r;
    r.x = ((uint32_t)t.x << 16) | (uint32_t)__bfloat16_as_ushort(__float2bfloat16(a.x));
    r.y = ((uint32_t)t.y << 16) | (uint32_t)__bfloat16_as_ushort(__float2bfloat16(a.y));
    r.z = ((uint32_t)t.z << 16) | (uint32_t)__bfloat16_as_ushort(__float2bfloat16(a.z));
    r.w = ((uint32_t)t.w << 16) | (uint32_t)__bfloat16_as_ushort(__float2bfloat16(a.w));
    *(uint4*)(out + i) = r;
}

// ---------------------------------------------------------------------------
// fp16 GEMM, 1 MMA/fragment: C = A(fp16) @ B(fp16)^T, fp32 accum.
// 128x128 tile, 8 warps (4x2), K-chunk 32, LDG-prefetch double buffer.
// mode 0: fp32 Cout. mode 1: QKV epilogue -> Q (*0.125), K, V [b,h,d,t]
//   key-permuted, all single fp16.
// smem: mainloop 2*BUF_B = 40960; V-epilogue transpose 67584 -> 69632.
// ---------------------------------------------------------------------------
#define KC 32
#define LDP 40
#define TILE_B (128 * LDP * 2)          // 10240
#define BUF_B  (2 * TILE_B)             // A, B
#define SHM_GEMM 69632

__global__ __launch_bounds__(256)
void mma_gemm(const __half* __restrict__ A, const __half* __restrict__ B,
              int Ncols, float* __restrict__ Cout, int mode) {
    extern __shared__ char smem[];
    uint32_t sb = smem_u32(smem);
    int tid = threadIdx.x, wid = tid >> 5, lane = tid & 31;
    int wm = wid & 3, wn = wid >> 2;
    int m0 = blockIdx.y * 128, n0 = blockIdx.x * 128;

    int r_ld  = tid >> 2;
    int c8_ld = (tid & 3) * 8;
    const __half* srcs[2] = { A + (size_t)m0 * GK, B + (size_t)n0 * GK };

    uint32_t a_off = (uint32_t)((wm * 32 + (lane & 15)) * LDP + (lane >> 4) * 8) * 2;
    uint32_t b_off = (uint32_t)((wn * 64 + (lane & 7) + (lane >> 4) * 8) * LDP
                                + ((lane >> 3) & 1) * 8) * 2;

    float acc[2][8][4];
#pragma unroll
    for (int i = 0; i < 2; i++)
#pragma unroll
        for (int j = 0; j < 8; j++)
#pragma unroll
            for (int k = 0; k < 4; k++) acc[i][j][k] = 0.f;

    uint4 pf[2][2];
#pragma unroll
    for (int t = 0; t < 2; t++)
#pragma unroll
        for (int i = 0; i < 2; i++)
            pf[t][i] = *(const uint4*)(srcs[t] + (size_t)(r_ld + i * 64) * GK + c8_ld);
    {
        char* base = smem;
#pragma unroll
        for (int t = 0; t < 2; t++)
#pragma unroll
            for (int i = 0; i < 2; i++)
                *(uint4*)(base + t * TILE_B + ((r_ld + i * 64) * LDP + c8_ld) * 2) = pf[t][i];
    }
    __syncthreads();

    const int NCH = GK / KC;
    for (int kc = 0; kc < NCH; kc++) {
        int buf = kc & 1;
        if (kc + 1 < NCH) {
            size_t go = (size_t)(kc + 1) * KC;
#pragma unroll
            for (int t = 0; t < 2; t++)
#pragma unroll
                for (int i = 0; i < 2; i++)
                    pf[t][i] = *(const uint4*)(srcs[t] + (size_t)(r_ld + i * 64) * GK + go + c8_ld);
        }
        uint32_t sA = sb + buf * BUF_B + a_off;
        uint32_t sBB = sb + buf * BUF_B + TILE_B + b_off;
#pragma unroll
        for (int ks = 0; ks < 2; ks++) {
            uint32_t kb = (uint32_t)(ks * 16) * 2;
            uint32_t ah[2][4];
#pragma unroll
            for (int tm = 0; tm < 2; tm++) {
                uint32_t ro = (uint32_t)(tm * 16 * LDP) * 2;
                ldsm4(ah[tm], sA + ro + kb);
            }
#pragma unroll
            for (int pr = 0; pr < 4; pr++) {
                uint32_t po = (uint32_t)(pr * 16 * LDP) * 2;
                uint32_t bb[4];
                ldsm4(bb, sBB + po + kb);
#pragma unroll
                for (int hf = 0; hf < 2; hf++) {
                    int tn = pr * 2 + hf;
#pragma unroll
                    for (int tm = 0; tm < 2; tm++)
                        mma16816h(acc[tm][tn], ah[tm], bb + hf * 2);
                }
            }
        }
        if (kc + 1 < NCH) {
            char* base = smem + (1 - buf) * BUF_B;
#pragma unroll
            for (int t = 0; t < 2; t++)
#pragma unroll
                for (int i = 0; i < 2; i++)
                    *(uint4*)(base + t * TILE_B + ((r_ld + i * 64) * LDP + c8_ld) * 2) = pf[t][i];
            __syncthreads();
        }
    }

    int rbase = m0 + wm * 32 + (lane >> 2);
    int cbase = n0 + wn * 64 + (lane & 3) * 2;

    if (mode == 0) {
#pragma unroll
        for (int tm = 0; tm < 2; tm++)
#pragma unroll
            for (int tn = 0; tn < 8; tn++)
#pragma unroll
                for (int half = 0; half < 2; half++) {
                    int m = rbase + tm * 16 + half * 8;
                    *(float2*)&Cout[(size_t)m * Ncols + cbase + tn * 8] =
                        make_float2(acc[tm][tn][half * 2], acc[tm][tn][half * 2 + 1]);
                }
        return;
    }

    int which = n0 >> 10;
    if (which < 2) {
        float sc = (which == 0) ? 0.125f : 1.0f;
        __half* dst = which ? g_k16 : g_q16;
#pragma unroll
        for (int tm = 0; tm < 2; tm++)
#pragma unroll
            for (int tn = 0; tn < 8; tn++)
#pragma unroll
                for (int half = 0; half < 2; half++) {
                    int m = rbase + tm * 16 + half * 8;
                    int n = cbase + tn * 8;
                    int h = (n & 1023) >> 6, d = n & 63;
                    int bI = m >> 11, t = m & 2047;
                    size_t ix = ((size_t)(bI * Hh + h) * Tt + t) * HDd + d;
                    *(uint32_t*)&dst[ix] =
                        h2u(acc[tm][tn][half * 2] * sc, acc[tm][tn][half * 2 + 1] * sc);
                }
    } else {
        // V: transpose via smem (float [128][132] <= SHM_GEMM),
        // store single fp16 [b,h,d,t] key-permuted
        float* buf = (float*)smem;
        __syncthreads();
#pragma unroll
        for (int tm = 0; tm < 2; tm++)
#pragma unroll
            for (int tn = 0; tn < 8; tn++)
#pragma unroll
                for (int half = 0; half < 2; half++) {
                    int nl = wn * 64 + tn * 8 + (lane & 3) * 2;
                    int ml = wm * 32 + (lane >> 2) + tm * 16 + half * 8;
                    buf[nl * 132 + ml]       = acc[tm][tn][half * 2];
                    buf[(nl + 1) * 132 + ml] = acc[tm][tn][half * 2 + 1];
                }
        __syncthreads();
        int nl = tid >> 1, mh = (tid & 1) * 64;
        int n = n0 + nl;
        int h = (n & 1023) >> 6, d = n & 63;
        int bI = m0 >> 11, t0 = (m0 & 2047) + mh;
        size_t base = ((size_t)(bI * Hh + h) * HDd + d) * Tt + t0;
#pragma unroll
        for (int g = 0; g < 8; g++) {
            __half v8[8];
#pragma unroll
            for (int e = 0; e < 8; e++) {
                int c = g * 8 + e;
                int src = 16 * ((c >> 1) & 3) + 2 * (c >> 3) + (c & 1);
                v8[e] = __float2half_rn(buf[nl * 132 + mh + src]);
            }
            *(uint4*)&g_v16[base + g * 8] = *(uint4*)v8;
        }
    }
}

// ---------------------------------------------------------------------------
// Flash attention: QK^T = Q(single) x K(single) = 1 MMA; PV = P(single) x
// V(single) = 1 MMA. cp.async KV double-buffer, LPT, pipelined bias.
// ---------------------------------------------------------------------------
#define LQ 72
#define QB (128 * LQ * 2)
#define TB (64 * LQ * 2)
#define OKV QB

__global__ __launch_bounds__(256, 2) void attn_mma(
    const uint32_t* __restrict__ pk, const float* __restrict__ adj_bias,
    const float* __restrict__ edge_table) {
    extern __shared__ char sm[];
    uint32_t sB = smem_u32(sm);
    float* ets = (float*)(sm + OKV + 4 * TB);

    int tid = threadIdx.x, w = tid >> 5, lane = tid & 31;
    int qt = (int)(gridDim.x - 1 - blockIdx.x);
    int h = blockIdx.y, b = blockIdx.z;
    int q0 = qt * 128, qw = q0 + 16 * w;
    float bco = adj_bias[h];
    if (tid < NEe) ets[tid] = edge_table[tid * Hh + h];

    {   // Q tile (single fp16, pre-scaled)
        const __half* qp = g_q16 + ((size_t)(b * Hh + h) * Tt + q0) * HDd;
        __half* sQ = (__half*)sm;
        int r = tid >> 1, cg = (tid & 1) * 32;
#pragma unroll
        for (int u = 0; u < 4; u++)
            *(uint4*)&sQ[r * LQ + cg + u * 8] = *(const uint4*)&qp[(size_t)r * 64 + cg + u * 8];
    }

    int c = tid >> 2, dg = (tid & 3) * 16;
    int gkp = 16 * ((c >> 1) & 3) + 2 * (c >> 3) + (c & 1);
    uint32_t krow = (uint32_t)(c * LQ + dg) * 2;
    const __half* bk = g_k16 + ((size_t)(b * Hh + h) * Tt + gkp) * HDd + dg;
    const __half* bv = g_v16 + ((size_t)(b * Hh + h) * HDd + c) * Tt + dg;

#define LOADKV(jt, bf) do {                                                     \
    int _k0 = (jt) * 64;                                                        \
    uint32_t _bs = sB + OKV + (bf) * 2 * TB;                                    \
    cpa16(_bs + krow,          bk + (size_t)_k0 * HDd);                         \
    cpa16(_bs + krow + 16,     bk + (size_t)_k0 * HDd + 8);                     \
    cpa16(_bs + TB + krow,     bv + _k0);                                       \
    cpa16(_bs + TB + krow + 16, bv + _k0 + 8);                                  \
    CPC();                                                                      \
} while (0)

    float o[8][4];
#pragma unroll
    for (int i = 0; i < 8; i++)
#pragma unroll
        for (int j = 0; j < 4; j++) o[i][j] = 0.f;
    float m0r = -1e30f, m1r = -1e30f, l0r = 0.f, l1r = 0.f;

    LOADKV(0, 0);

    int a = lane & 3, grp = lane >> 2;
    const uint32_t* pkb = pk + ((size_t)b * Tt + qw + grp) * Tt + 16 * a;

    int nkt = 2 * qt + 2;
    for (int jt = 0; jt < nkt; jt++) {
        int k0 = jt * 64;
        int buf = jt & 1;
        CPW0();
        __syncthreads();
        if (jt + 1 < nkt) LOADKV(jt + 1, buf ^ 1);

        if (k0 > qw + 15) continue;

        uint32_t oK = OKV + buf * 2 * TB, oV = oK + TB;

        uint4 u0[4];
        {
            const uint4* bp0 = (const uint4*)(pkb + k0);
            u0[0] = bp0[0]; u0[1] = bp0[1]; u0[2] = bp0[2]; u0[3] = bp0[3];
        }

        float s[8][4];
#pragma unroll
        for (int i = 0; i < 8; i++)
#pragma unroll
            for (int j = 0; j < 4; j++) s[i][j] = 0.f;

        uint32_t acol = (uint32_t)((lane >> 4) * 8) * 2;
        uint32_t arow = (uint32_t)((16 * w + (lane & 15)) * LQ) * 2;
        uint32_t bro  = (uint32_t)(((lane & 7) + (lane >> 4) * 8) * LQ) * 2;
        uint32_t bco2 = (uint32_t)(((lane >> 3) & 1) * 8) * 2;
#pragma unroll
        for (int ck = 0; ck < 4; ck++) {
            uint32_t kb = (uint32_t)(ck * 16) * 2;
            uint32_t aq[4];
            ldsm4(aq, sB + arow + acol + kb);
#pragma unroll
            for (int pr = 0; pr < 4; pr++) {
                uint32_t ro = (uint32_t)(pr * 16 * LQ) * 2;
                uint32_t bb[4];
                ldsm4(bb, sB + oK + bro + ro + bco2 + kb);
#pragma unroll
                for (int hf = 0; hf < 2; hf++)
                    mma16816h(s[pr * 2 + hf], aq, bb + hf * 2);
            }
        }

        uint4 u1[4];
        {
            const uint4* bp1 = (const uint4*)(pkb + 8 * Tt + k0);
            u1[0] = bp1[0]; u1[1] = bp1[1]; u1[2] = bp1[2]; u1[3] = bp1[3];
        }

        bool mm = (k0 + 63 > qw);
        float alpha0, alpha1;
#pragma unroll
        for (int half = 0; half < 2; half++) {
            int q = qw + grp + 8 * half;
            const uint32_t* ub = (const uint32_t*)(half ? u1 : u0);
            float mx = -1e30f;
#pragma unroll
            for (int nt = 0; nt < 8; nt++)
#pragma unroll
                for (int e = 0; e < 2; e++) {
                    int kk = 2 * nt + e;
                    uint32_t pv = ub[kk];
                    float sv = s[nt][half * 2 + e] + bco * __uint_as_float(pv << 16)
                               + ets[pv >> 16];
                    if (mm && (k0 + 16 * a + kk > q)) sv = -1e30f;
                    s[nt][half * 2 + e] = sv;
                    mx = fmaxf(mx, sv);
                }
            mx = fmaxf(mx, __shfl_xor_sync(0xffffffffu, mx, 1));
            mx = fmaxf(mx, __shfl_xor_sync(0xffffffffu, mx, 2));
            float mold = half ? m1r : m0r;
            float mnew = fmaxf(mold, mx);
            float sum = 0.f;
#pragma unroll
            for (int nt = 0; nt < 8; nt++)
#pragma unroll
                for (int e = 0; e < 2; e++) {
                    float p = __expf(s[nt][half * 2 + e] - mnew);
                    s[nt][half * 2 + e] = p;
                    sum += p;
                }
            sum += __shfl_xor_sync(0xffffffffu, sum, 1);
            sum += __shfl_xor_sync(0xffffffffu, sum, 2);
            float al = __expf(mold - mnew);
            if (half == 0) { m0r = mnew; l0r = l0r * al + sum; alpha0 = al; }
            else           { m1r = mnew; l1r = l1r * al + sum; alpha1 = al; }
        }

#pragma unroll
        for (int nt = 0; nt < 8; nt++) {
            o[nt][0] *= alpha0; o[nt][1] *= alpha0;
            o[nt][2] *= alpha1; o[nt][3] *= alpha1;
        }
        // PV: P single x V single -> 1 MMA per fragment
#pragma unroll
        for (int j = 0; j < 4; j++) {
            uint32_t ph[4];
            ph[0] = h2u(s[2*j][0],   s[2*j][1]);
            ph[1] = h2u(s[2*j][2],   s[2*j][3]);
            ph[2] = h2u(s[2*j+1][0], s[2*j+1][1]);
            ph[3] = h2u(s[2*j+1][2], s[2*j+1][3]);
            uint32_t kb = (uint32_t)(j * 16) * 2;
#pragma unroll
            for (int pr = 0; pr < 4; pr++) {
                uint32_t ro = (uint32_t)(pr * 16 * LQ) * 2;
                uint32_t vv[4];
                ldsm4(vv, sB + oV + bro + ro + bco2 + kb);
#pragma unroll
                for (int hf = 0; hf < 2; hf++)
                    mma16816h(o[pr * 2 + hf], ph, vv + hf * 2);
            }
        }
    }

    // finalize -> single fp16 ao for proj GEMM
    float il0 = 1.f / l0r, il1 = 1.f / l1r;
    size_t ix = ((size_t)b * Tt + qw + grp) * Dd + h * 64 + a * 2;
#pragma unroll
    for (int nt = 0; nt < 8; nt++) {
        *(uint32_t*)&g_ao16[ix + nt * 8]          = h2u(o[nt][0] * il0, o[nt][1] * il0);
        *(uint32_t*)&g_ao16[ix + 8 * Dd + nt * 8] = h2u(o[nt][2] * il1, o[nt][3] * il1);
    }
}

// ---------------------------------------------------------------------------
extern "C" void kernel_launch(void* const* d_in, const int* in_sizes, int n_in,
                              void* d_out, int out_size) {
    const float* x     = (const float*)d_in[0];
    const float* gadj  = (const float*)d_in[1];
    const int*   etyp  = (const int*)d_in[2];
    const float* wqkv  = (const float*)d_in[3];
    const float* wproj = (const float*)d_in[4];
    const float* abias = (const float*)d_in[5];
    const float* etab  = (const float*)d_in[6];
    float* out = (float*)d_out;

    __half *x16, *wq16, *wp16, *ao16;
    uint32_t* packp;
    cudaGetSymbolAddress((void**)&x16,  g_x16);
    cudaGetSymbolAddress((void**)&wq16, g_wq16);
    cudaGetSymbolAddress((void**)&wp16, g_wp16);
    cudaGetSymbolAddress((void**)&ao16, g_ao16);
    cudaGetSymbolAddress((void**)&packp, g_pack);

    cudaFuncSetAttribute(mma_gemm, cudaFuncAttributeMaxDynamicSharedMemorySize, SHM_GEMM);
    const int SMA = OKV + 4 * TB + 128;   // 18432 + 36864 + 128 = 55424
    cudaFuncSetAttribute(attn_mma, cudaFuncAttributeMaxDynamicSharedMemorySize, SMA);

    cvt16<<<(Bb * Tt * Dd) / 1024, 256>>>(x, x16);
    transcvt16<<<dim3(3 * Dd / 32, Dd / 32), dim3(32, 8)>>>(wqkv, wq16, Dd, 3 * Dd);
    transcvt16<<<dim3(Dd / 32, Dd / 32), dim3(32, 8)>>>(wproj, wp16, Dd, Dd);
    pack_bias<<<(int)(((size_t)Bb * Tt * Tt) / 1024), 256>>>(gadj, etyp, packp);

    mma_gemm<<<dim3(3 * Dd / 128, Bb * Tt / 128), 256, SHM_GEMM>>>(
        x16, wq16, 3 * Dd, nullptr, 1);

    attn_mma<<<dim3(Tt / 128, Hh, Bb), 256, SMA>>>(packp, abias, etab);

    mma_gemm<<<dim3(Dd / 128, Bb * Tt / 128), 256, SHM_GEMM>>>(
        ao16, wp16, Dd, out, 0);
}

// round 16
// speedup vs baseline: 4.3254x; 1.0620x over previous
#include <cuda_runtime.h>
#include <cuda_bf16.h>
#include <cuda_fp16.h>
#include <math.h>
#include <cstdint>

#define Bb 2
#define Tt 2048
#define Dd 1024
#define Hh 16
#define HDd 64
#define NEe 17
#define GK 1024

// ---------------- scratch globals ----------------
__device__ __half g_x16[Bb*Tt*Dd];                                   // x single fp16
__device__ __half g_wq16[3*Dd*Dd];                                   // Wqkv^T fp16 single
__device__ __half g_wp16[Dd*Dd];                                     // Wproj^T fp16 single
__device__ __half g_ao16[Bb*Tt*Dd];                                  // attn out single fp16
__device__ __half g_q16[Bb*Hh*Tt*HDd];                               // [b,h,t,d] *0.125 single
__device__ __half g_k16[Bb*Hh*Tt*HDd];                               // [b,h,t,d] single
__device__ __half g_v16[Bb*Hh*Tt*HDd];                               // [b,h,d,t] single, key-permuted
__device__ uint32_t g_pack[(size_t)Bb*Tt*Tt];

// ---------------- helpers ----------------
__device__ __forceinline__ uint32_t smem_u32(const void* p) {
    uint32_t a;
    asm("{ .reg .u64 t; cvta.to.shared.u64 t, %1; cvt.u32.u64 %0, t; }" : "=r"(a) : "l"(p));
    return a;
}
__device__ __forceinline__ void ldsm4(uint32_t* r, uint32_t addr) {
    asm volatile("ldmatrix.sync.aligned.m8n8.x4.shared.b16 {%0,%1,%2,%3}, [%4];"
        : "=r"(r[0]), "=r"(r[1]), "=r"(r[2]), "=r"(r[3]) : "r"(addr));
}
__device__ __forceinline__ void mma16816h(float* c, const uint32_t* a, const uint32_t* b) {
    asm volatile("mma.sync.aligned.m16n8k16.row.col.f32.f16.f16.f32 "
        "{%0,%1,%2,%3}, {%4,%5,%6,%7}, {%8,%9}, {%0,%1,%2,%3};"
        : "+f"(c[0]), "+f"(c[1]), "+f"(c[2]), "+f"(c[3])
        : "r"(a[0]), "r"(a[1]), "r"(a[2]), "r"(a[3]), "r"(b[0]), "r"(b[1]));
}
__device__ __forceinline__ uint32_t h2u(float a, float b) {
    __half2 v = __floats2half2_rn(a, b);
    return *(uint32_t*)&v;
}
__device__ __forceinline__ void cpa16(uint32_t s, const void* g) {
    asm volatile("cp.async.cg.shared.global [%0], [%1], 16;" :: "r"(s), "l"(g));
}
#define CPC()  asm volatile("cp.async.commit_group;" ::: "memory")
#define CPW0() asm volatile("cp.async.wait_group 0;" ::: "memory")

// ---------------------------------------------------------------------------
// Fused prep: pack_bias (8192 blks, DRAM-bound, launched first) + cvt16 x
// (4096 blks) + transcvt Wqkv (3072 blks) + transcvt Wproj (1024 blks).
// ---------------------------------------------------------------------------
#define NB_PACK 8192
#define NB_CVT  4096
#define NB_WQ   3072
#define NB_WP   1024

__global__ __launch_bounds__(256) void prep_all(
    const float* __restrict__ x, const float* __restrict__ wqkv,
    const float* __restrict__ wproj, const float* __restrict__ adj,
    const int* __restrict__ ety) {
    __shared__ float t[32][33];
    int blk = blockIdx.x, tid = threadIdx.x;

    if (blk < NB_PACK) {
        size_t i = ((size_t)blk * 256 + tid) * 4;
        float4 a = *(const float4*)(adj + i);
        int4 tt = *(const int4*)(ety + i);
        uint4 r;
        r.x = ((uint32_t)tt.x << 16) | (uint32_t)__bfloat16_as_ushort(__float2bfloat16(a.x));
        r.y = ((uint32_t)tt.y << 16) | (uint32_t)__bfloat16_as_ushort(__float2bfloat16(a.y));
        r.z = ((uint32_t)tt.z << 16) | (uint32_t)__bfloat16_as_ushort(__float2bfloat16(a.z));
        r.w = ((uint32_t)tt.w << 16) | (uint32_t)__bfloat16_as_ushort(__float2bfloat16(a.w));
        *(uint4*)(g_pack + i) = r;
        return;
    }
    blk -= NB_PACK;
    if (blk < NB_CVT) {
        int i = (blk * 256 + tid) * 4;
        float4 v = *(const float4*)(x + i);
        *(__half2*)&g_x16[i]     = __floats2half2_rn(v.x, v.y);
        *(__half2*)&g_x16[i + 2] = __floats2half2_rn(v.z, v.w);
        return;
    }
    blk -= NB_CVT;

    // transpose+convert: W [Kdim, Ndim] -> Wt fp16 [Ndim, Kdim]
    const float* W;
    __half* tw;
    int Kdim = Dd, Ndim, bx, by;
    if (blk < NB_WQ) {
        W = wqkv; tw = g_wq16; Ndim = 3 * Dd;
        bx = blk % 96; by = blk / 96;
    } else {
        blk -= NB_WQ;
        W = wproj; tw = g_wp16; Ndim = Dd;
        bx = blk % 32; by = blk / 32;
    }
    int n0 = bx * 32, k0 = by * 32;
    int tx = tid & 31, ty = tid >> 5;
#pragma unroll
    for (int j = 0; j < 32; j += 8)
        t[ty + j][tx] = W[(size_t)(k0 + ty + j) * Ndim + n0 + tx];
    __syncthreads();
#pragma unroll
    for (int j = 0; j < 32; j += 8)
        tw[(size_t)(n0 + ty + j) * Kdim + k0 + tx] = __float2half_rn(t[tx][ty + j]);
}

// ---------------------------------------------------------------------------
// fp16 GEMM, 1 MMA/fragment, 128x128 tile, 2 CTAs/SM.
// mode 0: fp32 Cout. mode 1: QKV epilogue -> Q (*0.125), K, V [b,h,d,t]
//   key-permuted, all single fp16.
// smem: mainloop 2*BUF_B = 40960; V-epilogue transpose 67584 -> 69632.
// ---------------------------------------------------------------------------
#define KC 32
#define LDP 40
#define TILE_B (128 * LDP * 2)          // 10240
#define BUF_B  (2 * TILE_B)             // A, B
#define SHM_GEMM 69632

__global__ __launch_bounds__(256, 2)
void mma_gemm(const __half* __restrict__ A, const __half* __restrict__ B,
              int Ncols, float* __restrict__ Cout, int mode) {
    extern __shared__ char smem[];
    uint32_t sb = smem_u32(smem);
    int tid = threadIdx.x, wid = tid >> 5, lane = tid & 31;
    int wm = wid & 3, wn = wid >> 2;
    int m0 = blockIdx.y * 128, n0 = blockIdx.x * 128;

    int r_ld  = tid >> 2;
    int c8_ld = (tid & 3) * 8;
    const __half* srcs[2] = { A + (size_t)m0 * GK, B + (size_t)n0 * GK };

    uint32_t a_off = (uint32_t)((wm * 32 + (lane & 15)) * LDP + (lane >> 4) * 8) * 2;
    uint32_t b_off = (uint32_t)((wn * 64 + (lane & 7) + (lane >> 4) * 8) * LDP
                                + ((lane >> 3) & 1) * 8) * 2;

    float acc[2][8][4];
#pragma unroll
    for (int i = 0; i < 2; i++)
#pragma unroll
        for (int j = 0; j < 8; j++)
#pragma unroll
            for (int k = 0; k < 4; k++) acc[i][j][k] = 0.f;

    uint4 pf[2][2];
#pragma unroll
    for (int t = 0; t < 2; t++)
#pragma unroll
        for (int i = 0; i < 2; i++)
            pf[t][i] = *(const uint4*)(srcs[t] + (size_t)(r_ld + i * 64) * GK + c8_ld);
    {
        char* base = smem;
#pragma unroll
        for (int t = 0; t < 2; t++)
#pragma unroll
            for (int i = 0; i < 2; i++)
                *(uint4*)(base + t * TILE_B + ((r_ld + i * 64) * LDP + c8_ld) * 2) = pf[t][i];
    }
    __syncthreads();

    const int NCH = GK / KC;
    for (int kc = 0; kc < NCH; kc++) {
        int buf = kc & 1;
        if (kc + 1 < NCH) {
            size_t go = (size_t)(kc + 1) * KC;
#pragma unroll
            for (int t = 0; t < 2; t++)
#pragma unroll
                for (int i = 0; i < 2; i++)
                    pf[t][i] = *(const uint4*)(srcs[t] + (size_t)(r_ld + i * 64) * GK + go + c8_ld);
        }
        uint32_t sA = sb + buf * BUF_B + a_off;
        uint32_t sBB = sb + buf * BUF_B + TILE_B + b_off;
#pragma unroll
        for (int ks = 0; ks < 2; ks++) {
            uint32_t kb = (uint32_t)(ks * 16) * 2;
            uint32_t ah[2][4];
#pragma unroll
            for (int tm = 0; tm < 2; tm++) {
                uint32_t ro = (uint32_t)(tm * 16 * LDP) * 2;
                ldsm4(ah[tm], sA + ro + kb);
            }
#pragma unroll
            for (int pr = 0; pr < 4; pr++) {
                uint32_t po = (uint32_t)(pr * 16 * LDP) * 2;
                uint32_t bb[4];
                ldsm4(bb, sBB + po + kb);
#pragma unroll
                for (int hf = 0; hf < 2; hf++) {
                    int tn = pr * 2 + hf;
#pragma unroll
                    for (int tm = 0; tm < 2; tm++)
                        mma16816h(acc[tm][tn], ah[tm], bb + hf * 2);
                }
            }
        }
        if (kc + 1 < NCH) {
            char* base = smem + (1 - buf) * BUF_B;
#pragma unroll
            for (int t = 0; t < 2; t++)
#pragma unroll
                for (int i = 0; i < 2; i++)
                    *(uint4*)(base + t * TILE_B + ((r_ld + i * 64) * LDP + c8_ld) * 2) = pf[t][i];
            __syncthreads();
        }
    }

    int rbase = m0 + wm * 32 + (lane >> 2);
    int cbase = n0 + wn * 64 + (lane & 3) * 2;

    if (mode == 0) {
#pragma unroll
        for (int tm = 0; tm < 2; tm++)
#pragma unroll
            for (int tn = 0; tn < 8; tn++)
#pragma unroll
                for (int half = 0; half < 2; half++) {
                    int m = rbase + tm * 16 + half * 8;
                    *(float2*)&Cout[(size_t)m * Ncols + cbase + tn * 8] =
                        make_float2(acc[tm][tn][half * 2], acc[tm][tn][half * 2 + 1]);
                }
        return;
    }

    int which = n0 >> 10;
    if (which < 2) {
        float sc = (which == 0) ? 0.125f : 1.0f;
        __half* dst = which ? g_k16 : g_q16;
#pragma unroll
        for (int tm = 0; tm < 2; tm++)
#pragma unroll
            for (int tn = 0; tn < 8; tn++)
#pragma unroll
                for (int half = 0; half < 2; half++) {
                    int m = rbase + tm * 16 + half * 8;
                    int n = cbase + tn * 8;
                    int h = (n & 1023) >> 6, d = n & 63;
                    int bI = m >> 11, t = m & 2047;
                    size_t ix = ((size_t)(bI * Hh + h) * Tt + t) * HDd + d;
                    *(uint32_t*)&dst[ix] =
                        h2u(acc[tm][tn][half * 2] * sc, acc[tm][tn][half * 2 + 1] * sc);
                }
    } else {
        // V: transpose via smem (float [128][132] <= SHM_GEMM),
        // store single fp16 [b,h,d,t] key-permuted
        float* buf = (float*)smem;
        __syncthreads();
#pragma unroll
        for (int tm = 0; tm < 2; tm++)
#pragma unroll
            for (int tn = 0; tn < 8; tn++)
#pragma unroll
                for (int half = 0; half < 2; half++) {
                    int nl = wn * 64 + tn * 8 + (lane & 3) * 2;
                    int ml = wm * 32 + (lane >> 2) + tm * 16 + half * 8;
                    buf[nl * 132 + ml]       = acc[tm][tn][half * 2];
                    buf[(nl + 1) * 132 + ml] = acc[tm][tn][half * 2 + 1];
                }
        __syncthreads();
        int nl = tid >> 1, mh = (tid & 1) * 64;
        int n = n0 + nl;
        int h = (n & 1023) >> 6, d = n & 63;
        int bI = m0 >> 11, t0 = (m0 & 2047) + mh;
        size_t base = ((size_t)(bI * Hh + h) * HDd + d) * Tt + t0;
#pragma unroll
        for (int g = 0; g < 8; g++) {
            __half v8[8];
#pragma unroll
            for (int e = 0; e < 8; e++) {
                int c = g * 8 + e;
                int src = 16 * ((c >> 1) & 3) + 2 * (c >> 3) + (c & 1);
                v8[e] = __float2half_rn(buf[nl * 132 + mh + src]);
            }
            *(uint4*)&g_v16[base + g * 8] = *(uint4*)v8;
        }
    }
}

// ---------------------------------------------------------------------------
// Flash attention: QK^T = 1 MMA; PV = 1 MMA. cp.async KV double-buffer,
// LPT ordering, pipelined bias loads.
// ---------------------------------------------------------------------------
#define LQ 72
#define QB (128 * LQ * 2)
#define TB (64 * LQ * 2)
#define OKV QB

__global__ __launch_bounds__(256, 2) void attn_mma(
    const uint32_t* __restrict__ pk, const float* __restrict__ adj_bias,
    const float* __restrict__ edge_table) {
    extern __shared__ char sm[];
    uint32_t sB = smem_u32(sm);
    float* ets = (float*)(sm + OKV + 4 * TB);

    int tid = threadIdx.x, w = tid >> 5, lane = tid & 31;
    int qt = (int)(gridDim.x - 1 - blockIdx.x);
    int h = blockIdx.y, b = blockIdx.z;
    int q0 = qt * 128, qw = q0 + 16 * w;
    float bco = adj_bias[h];
    if (tid < NEe) ets[tid] = edge_table[tid * Hh + h];

    {   // Q tile (single fp16, pre-scaled)
        const __half* qp = g_q16 + ((size_t)(b * Hh + h) * Tt + q0) * HDd;
        __half* sQ = (__half*)sm;
        int r = tid >> 1, cg = (tid & 1) * 32;
#pragma unroll
        for (int u = 0; u < 4; u++)
            *(uint4*)&sQ[r * LQ + cg + u * 8] = *(const uint4*)&qp[(size_t)r * 64 + cg + u * 8];
    }

    int c = tid >> 2, dg = (tid & 3) * 16;
    int gkp = 16 * ((c >> 1) & 3) + 2 * (c >> 3) + (c & 1);
    uint32_t krow = (uint32_t)(c * LQ + dg) * 2;
    const __half* bk = g_k16 + ((size_t)(b * Hh + h) * Tt + gkp) * HDd + dg;
    const __half* bv = g_v16 + ((size_t)(b * Hh + h) * HDd + c) * Tt + dg;

#define LOADKV(jt, bf) do {                                                     \
    int _k0 = (jt) * 64;                                                        \
    uint32_t _bs = sB + OKV + (bf) * 2 * TB;                                    \
    cpa16(_bs + krow,          bk + (size_t)_k0 * HDd);                         \
    cpa16(_bs + krow + 16,     bk + (size_t)_k0 * HDd + 8);                     \
    cpa16(_bs + TB + krow,     bv + _k0);                                       \
    cpa16(_bs + TB + krow + 16, bv + _k0 + 8);                                  \
    CPC();                                                                      \
} while (0)

    float o[8][4];
#pragma unroll
    for (int i = 0; i < 8; i++)
#pragma unroll
        for (int j = 0; j < 4; j++) o[i][j] = 0.f;
    float m0r = -1e30f, m1r = -1e30f, l0r = 0.f, l1r = 0.f;

    LOADKV(0, 0);

    int a = lane & 3, grp = lane >> 2;
    const uint32_t* pkb = pk + ((size_t)b * Tt + qw + grp) * Tt + 16 * a;

    int nkt = 2 * qt + 2;
    for (int jt = 0; jt < nkt; jt++) {
        int k0 = jt * 64;
        int buf = jt & 1;
        CPW0();
        __syncthreads();
        if (jt + 1 < nkt) LOADKV(jt + 1, buf ^ 1);

        if (k0 > qw + 15) continue;

        uint32_t oK = OKV + buf * 2 * TB, oV = oK + TB;

        uint4 u0[4];
        {
            const uint4* bp0 = (const uint4*)(pkb + k0);
            u0[0] = bp0[0]; u0[1] = bp0[1]; u0[2] = bp0[2]; u0[3] = bp0[3];
        }

        float s[8][4];
#pragma unroll
        for (int i = 0; i < 8; i++)
#pragma unroll
            for (int j = 0; j < 4; j++) s[i][j] = 0.f;

        uint32_t acol = (uint32_t)((lane >> 4) * 8) * 2;
        uint32_t arow = (uint32_t)((16 * w + (lane & 15)) * LQ) * 2;
        uint32_t bro  = (uint32_t)(((lane & 7) + (lane >> 4) * 8) * LQ) * 2;
        uint32_t bco2 = (uint32_t)(((lane >> 3) & 1) * 8) * 2;
#pragma unroll
        for (int ck = 0; ck < 4; ck++) {
            uint32_t kb = (uint32_t)(ck * 16) * 2;
            uint32_t aq[4];
            ldsm4(aq, sB + arow + acol + kb);
#pragma unroll
            for (int pr = 0; pr < 4; pr++) {
                uint32_t ro = (uint32_t)(pr * 16 * LQ) * 2;
                uint32_t bb[4];
                ldsm4(bb, sB + oK + bro + ro + bco2 + kb);
#pragma unroll
                for (int hf = 0; hf < 2; hf++)
                    mma16816h(s[pr * 2 + hf], aq, bb + hf * 2);
            }
        }

        uint4 u1[4];
        {
            const uint4* bp1 = (const uint4*)(pkb + 8 * Tt + k0);
            u1[0] = bp1[0]; u1[1] = bp1[1]; u1[2] = bp1[2]; u1[3] = bp1[3];
        }

        bool mm = (k0 + 63 > qw);
        float alpha0, alpha1;
#pragma unroll
        for (int half = 0; half < 2; half++) {
            int q = qw + grp + 8 * half;
            const uint32_t* ub = (const uint32_t*)(half ? u1 : u0);
            float mx = -1e30f;
#pragma unroll
            for (int nt = 0; nt < 8; nt++)
#pragma unroll
                for (int e = 0; e < 2; e++) {
                    int kk = 2 * nt + e;
                    uint32_t pv = ub[kk];
                    float sv = s[nt][half * 2 + e] + bco * __uint_as_float(pv << 16)
                               + ets[pv >> 16];
                    if (mm && (k0 + 16 * a + kk > q)) sv = -1e30f;
                    s[nt][half * 2 + e] = sv;
                    mx = fmaxf(mx, sv);
                }
            mx = fmaxf(mx, __shfl_xor_sync(0xffffffffu, mx, 1));
            mx = fmaxf(mx, __shfl_xor_sync(0xffffffffu, mx, 2));
            float mold = half ? m1r : m0r;
            float mnew = fmaxf(mold, mx);
            float sum = 0.f;
#pragma unroll
            for (int nt = 0; nt < 8; nt++)
#pragma unroll
                for (int e = 0; e < 2; e++) {
                    float p = __expf(s[nt][half * 2 + e] - mnew);
                    s[nt][half * 2 + e] = p;
                    sum += p;
                }
            sum += __shfl_xor_sync(0xffffffffu, sum, 1);
            sum += __shfl_xor_sync(0xffffffffu, sum, 2);
            float al = __expf(mold - mnew);
            if (half == 0) { m0r = mnew; l0r = l0r * al + sum; alpha0 = al; }
            else           { m1r = mnew; l1r = l1r * al + sum; alpha1 = al; }
        }

#pragma unroll
        for (int nt = 0; nt < 8; nt++) {
            o[nt][0] *= alpha0; o[nt][1] *= alpha0;
            o[nt][2] *= alpha1; o[nt][3] *= alpha1;
        }
#pragma unroll
        for (int j = 0; j < 4; j++) {
            uint32_t ph[4];
            ph[0] = h2u(s[2*j][0],   s[2*j][1]);
            ph[1] = h2u(s[2*j][2],   s[2*j][3]);
            ph[2] = h2u(s[2*j+1][0], s[2*j+1][1]);
            ph[3] = h2u(s[2*j+1][2], s[2*j+1][3]);
            uint32_t kb = (uint32_t)(j * 16) * 2;
#pragma unroll
            for (int pr = 0; pr < 4; pr++) {
                uint32_t ro = (uint32_t)(pr * 16 * LQ) * 2;
                uint32_t vv[4];
                ldsm4(vv, sB + oV + bro + ro + bco2 + kb);
#pragma unroll
                for (int hf = 0; hf < 2; hf++)
                    mma16816h(o[pr * 2 + hf], ph, vv + hf * 2);
            }
        }
    }

    // finalize -> single fp16 ao for proj GEMM
    float il0 = 1.f / l0r, il1 = 1.f / l1r;
    size_t ix = ((size_t)b * Tt + qw + grp) * Dd + h * 64 + a * 2;
#pragma unroll
    for (int nt = 0; nt < 8; nt++) {
        *(uint32_t*)&g_ao16[ix + nt * 8]          = h2u(o[nt][0] * il0, o[nt][1] * il0);
        *(uint32_t*)&g_ao16[ix + 8 * Dd + nt * 8] = h2u(o[nt][2] * il1, o[nt][3] * il1);
    }
}

// ---------------------------------------------------------------------------
extern "C" void kernel_launch(void* const* d_in, const int* in_sizes, int n_in,
                              void* d_out, int out_size) {
    const float* x     = (const float*)d_in[0];
    const float* gadj  = (const float*)d_in[1];
    const int*   etyp  = (const int*)d_in[2];
    const float* wqkv  = (const float*)d_in[3];
    const float* wproj = (const float*)d_in[4];
    const float* abias = (const float*)d_in[5];
    const float* etab  = (const float*)d_in[6];
    float* out = (float*)d_out;

    __half *x16, *wq16, *wp16, *ao16;
    uint32_t* packp;
    cudaGetSymbolAddress((void**)&x16,  g_x16);
    cudaGetSymbolAddress((void**)&wq16, g_wq16);
    cudaGetSymbolAddress((void**)&wp16, g_wp16);
    cudaGetSymbolAddress((void**)&ao16, g_ao16);
    cudaGetSymbolAddress((void**)&packp, g_pack);

    cudaFuncSetAttribute(mma_gemm, cudaFuncAttributeMaxDynamicSharedMemorySize, SHM_GEMM);
    const int SMA = OKV + 4 * TB + 128;   // 55424
    cudaFuncSetAttribute(attn_mma, cudaFuncAttributeMaxDynamicSharedMemorySize, SMA);

    prep_all<<<NB_PACK + NB_CVT + NB_WQ + NB_WP, 256>>>(x, wqkv, wproj, gadj, etyp);

    mma_gemm<<<dim3(3 * Dd / 128, Bb * Tt / 128), 256, SHM_GEMM>>>(
        x16, wq16, 3 * Dd, nullptr, 1);

    attn_mma<<<dim3(Tt / 128, Hh, Bb), 256, SMA>>>(packp, abias, etab);

    mma_gemm<<<dim3(Dd / 128, Bb * Tt / 128), 256, SHM_GEMM>>>(
        ao16, wp16, Dd, out, 0);
}

// round 17
// speedup vs baseline: 4.4260x; 1.0233x over previous
#include <cuda_runtime.h>
#include <cuda_bf16.h>
#include <cuda_fp16.h>
#include <math.h>
#include <cstdint>

#define Bb 2
#define Tt 2048
#define Dd 1024
#define Hh 16
#define HDd 64
#define NEe 17
#define GK 1024

// ---------------- scratch globals ----------------
__device__ __half g_x16[Bb*Tt*Dd];
__device__ __half g_wq16[3*Dd*Dd];
__device__ __half g_wp16[Dd*Dd];
__device__ __half g_ao16[Bb*Tt*Dd];
__device__ __half g_q16[Bb*Hh*Tt*HDd];
__device__ __half g_k16[Bb*Hh*Tt*HDd];
__device__ __half g_v16[Bb*Hh*Tt*HDd];
__device__ uint32_t g_pack[(size_t)Bb*Tt*Tt];

// ---------------- helpers ----------------
__device__ __forceinline__ uint32_t smem_u32(const void* p) {
    uint32_t a;
    asm("{ .reg .u64 t; cvta.to.shared.u64 t, %1; cvt.u32.u64 %0, t; }" : "=r"(a) : "l"(p));
    return a;
}
__device__ __forceinline__ void ldsm4(uint32_t* r, uint32_t addr) {
    asm volatile("ldmatrix.sync.aligned.m8n8.x4.shared.b16 {%0,%1,%2,%3}, [%4];"
        : "=r"(r[0]), "=r"(r[1]), "=r"(r[2]), "=r"(r[3]) : "r"(addr));
}
__device__ __forceinline__ void mma16816h(float* c, const uint32_t* a, const uint32_t* b) {
    asm volatile("mma.sync.aligned.m16n8k16.row.col.f32.f16.f16.f32 "
        "{%0,%1,%2,%3}, {%4,%5,%6,%7}, {%8,%9}, {%0,%1,%2,%3};"
        : "+f"(c[0]), "+f"(c[1]), "+f"(c[2]), "+f"(c[3])
        : "r"(a[0]), "r"(a[1]), "r"(a[2]), "r"(a[3]), "r"(b[0]), "r"(b[1]));
}
__device__ __forceinline__ uint32_t h2u(float a, float b) {
    __half2 v = __floats2half2_rn(a, b);
    return *(uint32_t*)&v;
}
__device__ __forceinline__ void cpa16(uint32_t s, const void* g) {
    asm volatile("cp.async.cg.shared.global [%0], [%1], 16;" :: "r"(s), "l"(g));
}
#define CPC()  asm volatile("cp.async.commit_group;" ::: "memory")
#define CPW0() asm volatile("cp.async.wait_group 0;" ::: "memory")
#define CPW1() asm volatile("cp.async.wait_group 1;" ::: "memory")

// ---------------------------------------------------------------------------
// Fused prep
// ---------------------------------------------------------------------------
#define NB_PACK 8192
#define NB_CVT  4096
#define NB_WQ   3072
#define NB_WP   1024

__global__ __launch_bounds__(256) void prep_all(
    const float* __restrict__ x, const float* __restrict__ wqkv,
    const float* __restrict__ wproj, const float* __restrict__ adj,
    const int* __restrict__ ety) {
    __shared__ float t[32][33];
    int blk = blockIdx.x, tid = threadIdx.x;

    if (blk < NB_PACK) {
        size_t i = ((size_t)blk * 256 + tid) * 4;
        float4 a = *(const float4*)(adj + i);
        int4 tt = *(const int4*)(ety + i);
        uint4 r;
        r.x = ((uint32_t)tt.x << 16) | (uint32_t)__bfloat16_as_ushort(__float2bfloat16(a.x));
        r.y = ((uint32_t)tt.y << 16) | (uint32_t)__bfloat16_as_ushort(__float2bfloat16(a.y));
        r.z = ((uint32_t)tt.z << 16) | (uint32_t)__bfloat16_as_ushort(__float2bfloat16(a.z));
        r.w = ((uint32_t)tt.w << 16) | (uint32_t)__bfloat16_as_ushort(__float2bfloat16(a.w));
        *(uint4*)(g_pack + i) = r;
        return;
    }
    blk -= NB_PACK;
    if (blk < NB_CVT) {
        int i = (blk * 256 + tid) * 4;
        float4 v = *(const float4*)(x + i);
        *(__half2*)&g_x16[i]     = __floats2half2_rn(v.x, v.y);
        *(__half2*)&g_x16[i + 2] = __floats2half2_rn(v.z, v.w);
        return;
    }
    blk -= NB_CVT;

    const float* W;
    __half* tw;
    int Kdim = Dd, Ndim, bx, by;
    if (blk < NB_WQ) {
        W = wqkv; tw = g_wq16; Ndim = 3 * Dd;
        bx = blk % 96; by = blk / 96;
    } else {
        blk -= NB_WQ;
        W = wproj; tw = g_wp16; Ndim = Dd;
        bx = blk % 32; by = blk / 32;
    }
    int n0 = bx * 32, k0 = by * 32;
    int tx = tid & 31, ty = tid >> 5;
#pragma unroll
    for (int j = 0; j < 32; j += 8)
        t[ty + j][tx] = W[(size_t)(k0 + ty + j) * Ndim + n0 + tx];
    __syncthreads();
#pragma unroll
    for (int j = 0; j < 32; j += 8)
        tw[(size_t)(n0 + ty + j) * Kdim + k0 + tx] = __float2half_rn(t[tx][ty + j]);
}

// ---------------------------------------------------------------------------
// fp16 GEMM, 1 MMA/fragment, 128x128 tile, 3-stage cp.async pipeline,
// 2 CTAs/SM. mode 0: fp32 Cout. mode 1: QKV epilogue.
// Stage = A(128x32) + B(128x32) fp16, LDP-40 padded = 20480 B; 3 stages =
// 61440; V-epilogue transpose needs 67584 -> SHM 69632.
// ---------------------------------------------------------------------------
#define KC 32
#define LDP 40
#define TILE_B (128 * LDP * 2)          // 10240 per tensor per stage
#define STG_B  (2 * TILE_B)             // 20480 per stage
#define SHM_GEMM 69632

__global__ __launch_bounds__(256, 2)
void mma_gemm(const __half* __restrict__ A, const __half* __restrict__ B,
              int Ncols, float* __restrict__ Cout, int mode) {
    extern __shared__ char smem[];
    uint32_t sb = smem_u32(smem);
    int tid = threadIdx.x, wid = tid >> 5, lane = tid & 31;
    int wm = wid & 3, wn = wid >> 2;
    int m0 = blockIdx.y * 128, n0 = blockIdx.x * 128;

    int r_ld  = tid >> 2;                // 0..63
    int c8_ld = (tid & 3) * 8;           // half offset within 32-K chunk
    const __half* Aop = A + (size_t)m0 * GK;
    const __half* Bop = B + (size_t)n0 * GK;
    uint32_t dA0 = (uint32_t)(r_ld * LDP + c8_ld) * 2;
    uint32_t dA1 = (uint32_t)((r_ld + 64) * LDP + c8_ld) * 2;

#define GISSUE(st, kcc) do {                                                  \
    uint32_t _bs = sb + (uint32_t)(st) * STG_B;                               \
    size_t _go = (size_t)(kcc) * KC + c8_ld;                                  \
    cpa16(_bs + dA0,          Aop + (size_t)r_ld * GK + _go);                 \
    cpa16(_bs + dA1,          Aop + (size_t)(r_ld + 64) * GK + _go);          \
    cpa16(_bs + TILE_B + dA0, Bop + (size_t)r_ld * GK + _go);                 \
    cpa16(_bs + TILE_B + dA1, Bop + (size_t)(r_ld + 64) * GK + _go);          \
    CPC();                                                                    \
} while (0)

    uint32_t a_off = (uint32_t)((wm * 32 + (lane & 15)) * LDP + (lane >> 4) * 8) * 2;
    uint32_t b_off = (uint32_t)((wn * 64 + (lane & 7) + (lane >> 4) * 8) * LDP
                                + ((lane >> 3) & 1) * 8) * 2;

    float acc[2][8][4];
#pragma unroll
    for (int i = 0; i < 2; i++)
#pragma unroll
        for (int j = 0; j < 8; j++)
#pragma unroll
            for (int k = 0; k < 4; k++) acc[i][j][k] = 0.f;

    GISSUE(0, 0);
    GISSUE(1, 1);

    const int NCH = GK / KC;   // 32
    int st = 0;
    for (int kc = 0; kc < NCH; kc++) {
        if (kc + 1 < NCH) CPW1(); else CPW0();
        __syncthreads();
        if (kc + 2 < NCH) {
            int st2 = st + 2; if (st2 >= 3) st2 -= 3;
            GISSUE(st2, kc + 2);
        }
        uint32_t sA  = sb + (uint32_t)st * STG_B + a_off;
        uint32_t sBB = sb + (uint32_t)st * STG_B + TILE_B + b_off;
#pragma unroll
        for (int ks = 0; ks < 2; ks++) {
            uint32_t kb = (uint32_t)(ks * 16) * 2;
            uint32_t ah[2][4];
#pragma unroll
            for (int tm = 0; tm < 2; tm++) {
                uint32_t ro = (uint32_t)(tm * 16 * LDP) * 2;
                ldsm4(ah[tm], sA + ro + kb);
            }
#pragma unroll
            for (int pr = 0; pr < 4; pr++) {
                uint32_t po = (uint32_t)(pr * 16 * LDP) * 2;
                uint32_t bb[4];
                ldsm4(bb, sBB + po + kb);
#pragma unroll
                for (int hf = 0; hf < 2; hf++) {
                    int tn = pr * 2 + hf;
#pragma unroll
                    for (int tm = 0; tm < 2; tm++)
                        mma16816h(acc[tm][tn], ah[tm], bb + hf * 2);
                }
            }
        }
        if (++st >= 3) st = 0;
    }

    int rbase = m0 + wm * 32 + (lane >> 2);
    int cbase = n0 + wn * 64 + (lane & 3) * 2;

    if (mode == 0) {
#pragma unroll
        for (int tm = 0; tm < 2; tm++)
#pragma unroll
            for (int tn = 0; tn < 8; tn++)
#pragma unroll
                for (int half = 0; half < 2; half++) {
                    int m = rbase + tm * 16 + half * 8;
                    *(float2*)&Cout[(size_t)m * Ncols + cbase + tn * 8] =
                        make_float2(acc[tm][tn][half * 2], acc[tm][tn][half * 2 + 1]);
                }
        return;
    }

    int which = n0 >> 10;
    if (which < 2) {
        float sc = (which == 0) ? 0.125f : 1.0f;
        __half* dst = which ? g_k16 : g_q16;
#pragma unroll
        for (int tm = 0; tm < 2; tm++)
#pragma unroll
            for (int tn = 0; tn < 8; tn++)
#pragma unroll
                for (int half = 0; half < 2; half++) {
                    int m = rbase + tm * 16 + half * 8;
                    int n = cbase + tn * 8;
                    int h = (n & 1023) >> 6, d = n & 63;
                    int bI = m >> 11, t = m & 2047;
                    size_t ix = ((size_t)(bI * Hh + h) * Tt + t) * HDd + d;
                    *(uint32_t*)&dst[ix] =
                        h2u(acc[tm][tn][half * 2] * sc, acc[tm][tn][half * 2 + 1] * sc);
                }
    } else {
        float* buf = (float*)smem;
        __syncthreads();
#pragma unroll
        for (int tm = 0; tm < 2; tm++)
#pragma unroll
            for (int tn = 0; tn < 8; tn++)
#pragma unroll
                for (int half = 0; half < 2; half++) {
                    int nl = wn * 64 + tn * 8 + (lane & 3) * 2;
                    int ml = wm * 32 + (lane >> 2) + tm * 16 + half * 8;
                    buf[nl * 132 + ml]       = acc[tm][tn][half * 2];
                    buf[(nl + 1) * 132 + ml] = acc[tm][tn][half * 2 + 1];
                }
        __syncthreads();
        int nl = tid >> 1, mh = (tid & 1) * 64;
        int n = n0 + nl;
        int h = (n & 1023) >> 6, d = n & 63;
        int bI = m0 >> 11, t0 = (m0 & 2047) + mh;
        size_t base = ((size_t)(bI * Hh + h) * HDd + d) * Tt + t0;
#pragma unroll
        for (int g = 0; g < 8; g++) {
            __half v8[8];
#pragma unroll
            for (int e = 0; e < 8; e++) {
                int c = g * 8 + e;
                int src = 16 * ((c >> 1) & 3) + 2 * (c >> 3) + (c & 1);
                v8[e] = __float2half_rn(buf[nl * 132 + mh + src]);
            }
            *(uint4*)&g_v16[base + g * 8] = *(uint4*)v8;
        }
    }
}

// ---------------------------------------------------------------------------
// Flash attention (unchanged from R16): 1-MMA QK^T, 1-MMA PV, cp.async KV,
// LPT, pipelined bias.
// ---------------------------------------------------------------------------
#define LQ 72
#define QB (128 * LQ * 2)
#define TB (64 * LQ * 2)
#define OKV QB

__global__ __launch_bounds__(256, 2) void attn_mma(
    const uint32_t* __restrict__ pk, const float* __restrict__ adj_bias,
    const float* __restrict__ edge_table) {
    extern __shared__ char sm[];
    uint32_t sB = smem_u32(sm);
    float* ets = (float*)(sm + OKV + 4 * TB);

    int tid = threadIdx.x, w = tid >> 5, lane = tid & 31;
    int qt = (int)(gridDim.x - 1 - blockIdx.x);
    int h = blockIdx.y, b = blockIdx.z;
    int q0 = qt * 128, qw = q0 + 16 * w;
    float bco = adj_bias[h];
    if (tid < NEe) ets[tid] = edge_table[tid * Hh + h];

    {
        const __half* qp = g_q16 + ((size_t)(b * Hh + h) * Tt + q0) * HDd;
        __half* sQ = (__half*)sm;
        int r = tid >> 1, cg = (tid & 1) * 32;
#pragma unroll
        for (int u = 0; u < 4; u++)
            *(uint4*)&sQ[r * LQ + cg + u * 8] = *(const uint4*)&qp[(size_t)r * 64 + cg + u * 8];
    }

    int c = tid >> 2, dg = (tid & 3) * 16;
    int gkp = 16 * ((c >> 1) & 3) + 2 * (c >> 3) + (c & 1);
    uint32_t krow = (uint32_t)(c * LQ + dg) * 2;
    const __half* bk = g_k16 + ((size_t)(b * Hh + h) * Tt + gkp) * HDd + dg;
    const __half* bv = g_v16 + ((size_t)(b * Hh + h) * HDd + c) * Tt + dg;

#define LOADKV(jt, bf) do {                                                     \
    int _k0 = (jt) * 64;                                                        \
    uint32_t _bs = sB + OKV + (bf) * 2 * TB;                                    \
    cpa16(_bs + krow,          bk + (size_t)_k0 * HDd);                         \
    cpa16(_bs + krow + 16,     bk + (size_t)_k0 * HDd + 8);                     \
    cpa16(_bs + TB + krow,     bv + _k0);                                       \
    cpa16(_bs + TB + krow + 16, bv + _k0 + 8);                                  \
    CPC();                                                                      \
} while (0)

    float o[8][4];
#pragma unroll
    for (int i = 0; i < 8; i++)
#pragma unroll
        for (int j = 0; j < 4; j++) o[i][j] = 0.f;
    float m0r = -1e30f, m1r = -1e30f, l0r = 0.f, l1r = 0.f;

    LOADKV(0, 0);

    int a = lane & 3, grp = lane >> 2;
    const uint32_t* pkb = pk + ((size_t)b * Tt + qw + grp) * Tt + 16 * a;

    int nkt = 2 * qt + 2;
    for (int jt = 0; jt < nkt; jt++) {
        int k0 = jt * 64;
        int buf = jt & 1;
        CPW0();
        __syncthreads();
        if (jt + 1 < nkt) LOADKV(jt + 1, buf ^ 1);

        if (k0 > qw + 15) continue;

        uint32_t oK = OKV + buf * 2 * TB, oV = oK + TB;

        uint4 u0[4];
        {
            const uint4* bp0 = (const uint4*)(pkb + k0);
            u0[0] = bp0[0]; u0[1] = bp0[1]; u0[2] = bp0[2]; u0[3] = bp0[3];
        }

        float s[8][4];
#pragma unroll
        for (int i = 0; i < 8; i++)
#pragma unroll
            for (int j = 0; j < 4; j++) s[i][j] = 0.f;

        uint32_t acol = (uint32_t)((lane >> 4) * 8) * 2;
        uint32_t arow = (uint32_t)((16 * w + (lane & 15)) * LQ) * 2;
        uint32_t bro  = (uint32_t)(((lane & 7) + (lane >> 4) * 8) * LQ) * 2;
        uint32_t bco2 = (uint32_t)(((lane >> 3) & 1) * 8) * 2;
#pragma unroll
        for (int ck = 0; ck < 4; ck++) {
            uint32_t kb = (uint32_t)(ck * 16) * 2;
            uint32_t aq[4];
            ldsm4(aq, sB + arow + acol + kb);
#pragma unroll
            for (int pr = 0; pr < 4; pr++) {
                uint32_t ro = (uint32_t)(pr * 16 * LQ) * 2;
                uint32_t bb[4];
                ldsm4(bb, sB + oK + bro + ro + bco2 + kb);
#pragma unroll
                for (int hf = 0; hf < 2; hf++)
                    mma16816h(s[pr * 2 + hf], aq, bb + hf * 2);
            }
        }

        uint4 u1[4];
        {
            const uint4* bp1 = (const uint4*)(pkb + 8 * Tt + k0);
            u1[0] = bp1[0]; u1[1] = bp1[1]; u1[2] = bp1[2]; u1[3] = bp1[3];
        }

        bool mm = (k0 + 63 > qw);
        float alpha0, alpha1;
#pragma unroll
        for (int half = 0; half < 2; half++) {
            int q = qw + grp + 8 * half;
            const uint32_t* ub = (const uint32_t*)(half ? u1 : u0);
            float mx = -1e30f;
#pragma unroll
            for (int nt = 0; nt < 8; nt++)
#pragma unroll
                for (int e = 0; e < 2; e++) {
                    int kk = 2 * nt + e;
                    uint32_t pv = ub[kk];
                    float sv = s[nt][half * 2 + e] + bco * __uint_as_float(pv << 16)
                               + ets[pv >> 16];
                    if (mm && (k0 + 16 * a + kk > q)) sv = -1e30f;
                    s[nt][half * 2 + e] = sv;
                    mx = fmaxf(mx, sv);
                }
            mx = fmaxf(mx, __shfl_xor_sync(0xffffffffu, mx, 1));
            mx = fmaxf(mx, __shfl_xor_sync(0xffffffffu, mx, 2));
            float mold = half ? m1r : m0r;
            float mnew = fmaxf(mold, mx);
            float sum = 0.f;
#pragma unroll
            for (int nt = 0; nt < 8; nt++)
#pragma unroll
                for (int e = 0; e < 2; e++) {
                    float p = __expf(s[nt][half * 2 + e] - mnew);
                    s[nt][half * 2 + e] = p;
                    sum += p;
                }
            sum += __shfl_xor_sync(0xffffffffu, sum, 1);
            sum += __shfl_xor_sync(0xffffffffu, sum, 2);
            float al = __expf(mold - mnew);
            if (half == 0) { m0r = mnew; l0r = l0r * al + sum; alpha0 = al; }
            else           { m1r = mnew; l1r = l1r * al + sum; alpha1 = al; }
        }

#pragma unroll
        for (int nt = 0; nt < 8; nt++) {
            o[nt][0] *= alpha0; o[nt][1] *= alpha0;
            o[nt][2] *= alpha1; o[nt][3] *= alpha1;
        }
#pragma unroll
        for (int j = 0; j < 4; j++) {
            uint32_t ph[4];
            ph[0] = h2u(s[2*j][0],   s[2*j][1]);
            ph[1] = h2u(s[2*j][2],   s[2*j][3]);
            ph[2] = h2u(s[2*j+1][0], s[2*j+1][1]);
            ph[3] = h2u(s[2*j+1][2], s[2*j+1][3]);
            uint32_t kb = (uint32_t)(j * 16) * 2;
#pragma unroll
            for (int pr = 0; pr < 4; pr++) {
                uint32_t ro = (uint32_t)(pr * 16 * LQ) * 2;
                uint32_t vv[4];
                ldsm4(vv, sB + oV + bro + ro + bco2 + kb);
#pragma unroll
                for (int hf = 0; hf < 2; hf++)
                    mma16816h(o[pr * 2 + hf], ph, vv + hf * 2);
            }
        }
    }

    float il0 = 1.f / l0r, il1 = 1.f / l1r;
    size_t ix = ((size_t)b * Tt + qw + grp) * Dd + h * 64 + a * 2;
#pragma unroll
    for (int nt = 0; nt < 8; nt++) {
        *(uint32_t*)&g_ao16[ix + nt * 8]          = h2u(o[nt][0] * il0, o[nt][1] * il0);
        *(uint32_t*)&g_ao16[ix + 8 * Dd + nt * 8] = h2u(o[nt][2] * il1, o[nt][3] * il1);
    }
}

// ---------------------------------------------------------------------------
extern "C" void kernel_launch(void* const* d_in, const int* in_sizes, int n_in,
                              void* d_out, int out_size) {
    const float* x     = (const float*)d_in[0];
    const float* gadj  = (const float*)d_in[1];
    const int*   etyp  = (const int*)d_in[2];
    const float* wqkv  = (const float*)d_in[3];
    const float* wproj = (const float*)d_in[4];
    const float* abias = (const float*)d_in[5];
    const float* etab  = (const float*)d_in[6];
    float* out = (float*)d_out;

    __half *x16, *wq16, *wp16, *ao16;
    uint32_t* packp;
    cudaGetSymbolAddress((void**)&x16,  g_x16);
    cudaGetSymbolAddress((void**)&wq16, g_wq16);
    cudaGetSymbolAddress((void**)&wp16, g_wp16);
    cudaGetSymbolAddress((void**)&ao16, g_ao16);
    cudaGetSymbolAddress((void**)&packp, g_pack);

    cudaFuncSetAttribute(mma_gemm, cudaFuncAttributeMaxDynamicSharedMemorySize, SHM_GEMM);
    const int SMA = OKV + 4 * TB + 128;   // 55424
    cudaFuncSetAttribute(attn_mma, cudaFuncAttributeMaxDynamicSharedMemorySize, SMA);

    prep_all<<<NB_PACK + NB_CVT + NB_WQ + NB_WP, 256>>>(x, wqkv, wproj, gadj, etyp);

    mma_gemm<<<dim3(3 * Dd / 128, Bb * Tt / 128), 256, SHM_GEMM>>>(
        x16, wq16, 3 * Dd, nullptr, 1);

    attn_mma<<<dim3(Tt / 128, Hh, Bb), 256, SMA>>>(packp, abias, etab);

    mma_gemm<<<dim3(Dd / 128, Bb * Tt / 128), 256, SHM_GEMM>>>(
        ao16, wp16, Dd, out, 0);
}